// round 9
// baseline (speedup 1.0000x reference)
#include <cuda_runtime.h>
#include <math.h>

#define B_SZ 4096
#define D_SZ 32
#define H_SZ 1024
#define K_SZ 1024
#define MT   (B_SZ * D_SZ)   /* 131072 tangent rows (b,d) */

// ---------------- scratch (static device globals; no allocs) ----------------
__device__ float g_h1[B_SZ * H_SZ];                 // 16 MB
__device__ float g_h2[B_SZ * H_SZ];                 // 16 MB
__device__ float g_h3[B_SZ * H_SZ];                 // 16 MB
__device__ float g_U2[(size_t)MT * H_SZ];           // 512 MB
__device__ float g_tpart[8 * B_SZ];                 // per-(jtile, sample) trace partials

// ---------------- GEMM tiling ----------------
#define BM 128
#define BN 128
#define BK 16

__device__ __forceinline__ void sts_tile(float (*dst)[BM], const float4* v, int tid) {
#pragma unroll
    for (int l = 0; l < 2; l++) {
        int f = tid * 2 + l;
        int r = f >> 2, kq = f & 3;
        dst[kq * 4 + 0][r] = v[l].x;
        dst[kq * 4 + 1][r] = v[l].y;
        dst[kq * 4 + 2][r] = v[l].z;
        dst[kq * 4 + 3][r] = v[l].w;
    }
}

__device__ __forceinline__ void sts_t1(float (*dst)[BM], const float* v, int tid) {
#pragma unroll
    for (int i = 0; i < 8; i++) {
        int e = tid + i * 256;
        dst[e >> 7][e & 127] = v[i];
    }
}

// MODE 0: C = tanh(A @ W^T + bias)                     (forward hidden layers)
// MODE 1: C(=U2) = (1-hs^2) .* (U1 @ W^T), U1 generated on the fly from A(=h1), W0
// MODE 2: trace partials from (1-hs^2) .* (A(=U2) @ W^T) dotted with W3 rows
template <int MODE>
__global__ void __launch_bounds__(256, 2)
gemm_kernel(const float* __restrict__ A, const float* __restrict__ W,
            const float* __restrict__ bias, const float* __restrict__ hs,
            const float* __restrict__ W0p, const float* __restrict__ W3p,
            float* __restrict__ C)
{
    __shared__ float As[2][BK][BM];
    __shared__ float Bs[2][BK][BN];
    __shared__ float red[256];

    const int tid = threadIdx.x;
    const int tx = tid & 15, ty = tid >> 4;
    const int rowBase = blockIdx.y * BM;
    const int colBase = blockIdx.x * BN;

    float acc[8][8];
#pragma unroll
    for (int i = 0; i < 8; i++)
#pragma unroll
        for (int j = 0; j < 8; j++) acc[i][j] = 0.0f;

    // ---- prologue: load k-tile 0 into smem buffer 0 ----
    {
        float4 pb[2];
        if (MODE == 1) {
            float pt[8];
#pragma unroll
            for (int i = 0; i < 8; i++) {
                int e = tid + i * 256;
                int r = e & 127, kk = e >> 7;
                int grow = rowBase + r;
                float h = A[(size_t)(grow >> 5) * H_SZ + kk];
                pt[i] = (1.0f - h * h) * W0p[kk * 33 + (grow & 31)];
            }
            sts_t1(As[0], pt, tid);
        } else {
            float4 pa[2];
#pragma unroll
            for (int l = 0; l < 2; l++) {
                int f = tid * 2 + l;
                int r = f >> 2, kq = f & 3;
                pa[l] = *reinterpret_cast<const float4*>(A + (size_t)(rowBase + r) * K_SZ + kq * 4);
            }
            sts_tile(As[0], pa, tid);
        }
#pragma unroll
        for (int l = 0; l < 2; l++) {
            int f = tid * 2 + l;
            int r = f >> 2, kq = f & 3;
            pb[l] = *reinterpret_cast<const float4*>(W + (size_t)(colBase + r) * K_SZ + kq * 4);
        }
        sts_tile(Bs[0], pb, tid);
    }
    __syncthreads();

    // ---- main loop: double-buffered over 64 k-tiles ----
    const int NKT = K_SZ / BK;
    int cur = 0;
    for (int kt = 0; kt < NKT; kt++) {
        float4 na[2];
        float  nt[8];
        float4 nb[2];
        if (kt + 1 < NKT) {
            const int k0 = (kt + 1) * BK;
            if (MODE == 1) {
#pragma unroll
                for (int i = 0; i < 8; i++) {
                    int e = tid + i * 256;
                    int r = e & 127, kk = e >> 7;
                    int gk = k0 + kk;
                    int grow = rowBase + r;
                    float h = A[(size_t)(grow >> 5) * H_SZ + gk];
                    nt[i] = (1.0f - h * h) * W0p[gk * 33 + (grow & 31)];
                }
            } else {
#pragma unroll
                for (int l = 0; l < 2; l++) {
                    int f = tid * 2 + l;
                    int r = f >> 2, kq = f & 3;
                    na[l] = *reinterpret_cast<const float4*>(A + (size_t)(rowBase + r) * K_SZ + k0 + kq * 4);
                }
            }
#pragma unroll
            for (int l = 0; l < 2; l++) {
                int f = tid * 2 + l;
                int r = f >> 2, kq = f & 3;
                nb[l] = *reinterpret_cast<const float4*>(W + (size_t)(colBase + r) * K_SZ + k0 + kq * 4);
            }
        }

#pragma unroll
        for (int k = 0; k < BK; k++) {
            float av[8], bv[8];
            *reinterpret_cast<float4*>(&av[0]) = *reinterpret_cast<const float4*>(&As[cur][k][ty * 8]);
            *reinterpret_cast<float4*>(&av[4]) = *reinterpret_cast<const float4*>(&As[cur][k][ty * 8 + 4]);
            *reinterpret_cast<float4*>(&bv[0]) = *reinterpret_cast<const float4*>(&Bs[cur][k][tx * 8]);
            *reinterpret_cast<float4*>(&bv[4]) = *reinterpret_cast<const float4*>(&Bs[cur][k][tx * 8 + 4]);
#pragma unroll
            for (int i = 0; i < 8; i++)
#pragma unroll
                for (int j = 0; j < 8; j++)
                    acc[i][j] = fmaf(av[i], bv[j], acc[i][j]);
        }

        if (kt + 1 < NKT) {
            int nxt = cur ^ 1;
            if (MODE == 1) sts_t1(As[nxt], nt, tid);
            else           sts_tile(As[nxt], na, tid);
            sts_tile(Bs[nxt], nb, tid);
            __syncthreads();
            cur = nxt;
        }
    }

    // ---- epilogues ----
    if (MODE == 0) {
        const int c = colBase + tx * 8;
#pragma unroll
        for (int i = 0; i < 8; i++) {
            int r = rowBase + ty * 8 + i;
            float4 o0, o1;
            o0.x = tanhf(acc[i][0] + bias[c + 0]);
            o0.y = tanhf(acc[i][1] + bias[c + 1]);
            o0.z = tanhf(acc[i][2] + bias[c + 2]);
            o0.w = tanhf(acc[i][3] + bias[c + 3]);
            o1.x = tanhf(acc[i][4] + bias[c + 4]);
            o1.y = tanhf(acc[i][5] + bias[c + 5]);
            o1.z = tanhf(acc[i][6] + bias[c + 6]);
            o1.w = tanhf(acc[i][7] + bias[c + 7]);
            *reinterpret_cast<float4*>(C + (size_t)r * H_SZ + c)     = o0;
            *reinterpret_cast<float4*>(C + (size_t)r * H_SZ + c + 4) = o1;
        }
    } else if (MODE == 1) {
        const int bglob = (rowBase >> 5) + (ty >> 2);  // all 8 rows of this thread share one sample
        const int c = colBase + tx * 8;
        float sv[8];
#pragma unroll
        for (int j = 0; j < 8; j++) {
            float h = hs[(size_t)bglob * H_SZ + c + j];
            sv[j] = 1.0f - h * h;
        }
#pragma unroll
        for (int i = 0; i < 8; i++) {
            int r = rowBase + ty * 8 + i;
            float4 o0, o1;
            o0.x = acc[i][0] * sv[0];
            o0.y = acc[i][1] * sv[1];
            o0.z = acc[i][2] * sv[2];
            o0.w = acc[i][3] * sv[3];
            o1.x = acc[i][4] * sv[4];
            o1.y = acc[i][5] * sv[5];
            o1.z = acc[i][6] * sv[6];
            o1.w = acc[i][7] * sv[7];
            size_t base = (size_t)r * H_SZ + c;
            *reinterpret_cast<float4*>(C + base)     = o0;
            *reinterpret_cast<float4*>(C + base + 4) = o1;
        }
    } else {
        const int bglob = (rowBase >> 5) + (ty >> 2);
        float part = 0.0f;
#pragma unroll
        for (int j = 0; j < 8; j++) {
            int c = colBase + tx * 8 + j;
            float h = hs[(size_t)bglob * H_SZ + c];
            float s = 1.0f - h * h;
#pragma unroll
            for (int i = 0; i < 8; i++) {
                int d = (ty * 8 + i) & 31;
                part += W3p[d * H_SZ + c] * (acc[i][j] * s);
            }
        }
        red[tid] = part;
        __syncthreads();
        if (tid < 4) {
            float ssum = 0.0f;
#pragma unroll 8
            for (int t = 0; t < 64; t++) ssum += red[tid * 64 + t];
            // unique (jtile, sample) slot -> deterministic, no atomics
            g_tpart[blockIdx.x * B_SZ + (rowBase >> 5) + tid] = ssum;
        }
    }
}

// ---------------- small kernels ----------------

// h1 = tanh([z|t] @ W0^T + b0)
__global__ void layer0_kernel(const float* __restrict__ t, const float* __restrict__ z,
                              const float* __restrict__ W0, const float* __restrict__ b0,
                              float* __restrict__ h1)
{
    int idx = blockIdx.x * blockDim.x + threadIdx.x;   // B*H
    int j = idx & (H_SZ - 1);
    int b = idx >> 10;
    const float* w  = W0 + j * 33;
    const float* zr = z + b * D_SZ;
    float acc = b0[j] + t[0] * w[32];
#pragma unroll
    for (int d = 0; d < 32; d++) acc = fmaf(zr[d], w[d], acc);
    h1[idx] = tanhf(acc);
}

// out = h3 @ W3^T + b3
__global__ void out_kernel(const float* __restrict__ h3, const float* __restrict__ W3,
                           const float* __restrict__ b3, float* __restrict__ out)
{
    int idx = blockIdx.x * blockDim.x + threadIdx.x;   // B*D
    int d = idx & 31;
    int b = idx >> 5;
    const float* h = h3 + (size_t)b * H_SZ;
    const float* w = W3 + (size_t)d * H_SZ;
    float acc = 0.0f;
#pragma unroll 8
    for (int k = 0; k < H_SZ; k++) acc = fmaf(h[k], w[k], acc);
    out[idx] = acc + b3[d];
}

// divv[b] = -(sum of 8 j-tile partials)
__global__ void fin_kernel(float* __restrict__ out)
{
    int b = blockIdx.x * blockDim.x + threadIdx.x;
    if (b < B_SZ) {
        float s = 0.0f;
#pragma unroll
        for (int x = 0; x < 8; x++) s += g_tpart[x * B_SZ + b];
        out[B_SZ * D_SZ + b] = -s;
    }
}

// ---------------- launch ----------------
extern "C" void kernel_launch(void* const* d_in, const int* in_sizes, int n_in,
                              void* d_out, int out_size)
{
    const float* t  = (const float*)d_in[0];
    const float* z  = (const float*)d_in[1];
    const float* W0 = (const float*)d_in[2];
    const float* b0 = (const float*)d_in[3];
    const float* W1 = (const float*)d_in[4];
    const float* b1 = (const float*)d_in[5];
    const float* W2 = (const float*)d_in[6];
    const float* b2 = (const float*)d_in[7];
    const float* W3 = (const float*)d_in[8];
    const float* b3 = (const float*)d_in[9];
    float* out = (float*)d_out;

    float *ph1, *ph2, *ph3, *pU2;
    cudaGetSymbolAddress((void**)&ph1, g_h1);
    cudaGetSymbolAddress((void**)&ph2, g_h2);
    cudaGetSymbolAddress((void**)&ph3, g_h3);
    cudaGetSymbolAddress((void**)&pU2, g_U2);

    // forward
    layer0_kernel<<<(B_SZ * H_SZ) / 256, 256>>>(t, z, W0, b0, ph1);
    dim3 gF(H_SZ / BN, B_SZ / BM);           // (8, 32)
    gemm_kernel<0><<<gF, 256>>>(ph1, W1, b1, nullptr, nullptr, nullptr, ph2);
    gemm_kernel<0><<<gF, 256>>>(ph2, W2, b2, nullptr, nullptr, nullptr, ph3);
    out_kernel<<<(B_SZ * D_SZ) / 256, 256>>>(ph3, W3, b3, out);

    // tangent (JVP) chain: U2 = (1-h2^2) .* ((a1 .* W0') @ W1^T); trace from W2/W3
    dim3 gT(H_SZ / BN, MT / BM);             // (8, 1024)
    gemm_kernel<1><<<gT, 256>>>(ph1, W1, nullptr, ph2, W0, nullptr, pU2);
    gemm_kernel<2><<<gT, 256>>>(pU2, W2, nullptr, ph3, nullptr, W3, nullptr);

    fin_kernel<<<(B_SZ + 255) / 256, 256>>>(out);
}

// round 10
// speedup vs baseline: 1.0039x; 1.0039x over previous
#include <cuda_runtime.h>
#include <math.h>

#define B_SZ 4096
#define D_SZ 32
#define H_SZ 1024
#define K_SZ 1024
#define MT   (B_SZ * D_SZ)   /* 131072 tangent rows (b,d) */

// ---------------- scratch (static device globals; no allocs) ----------------
__device__ float g_h1[B_SZ * H_SZ];                 // 16 MB
__device__ float g_h2[B_SZ * H_SZ];                 // 16 MB
__device__ float g_h3[B_SZ * H_SZ];                 // 16 MB
__device__ float g_U2[(size_t)MT * H_SZ];           // 512 MB
__device__ float g_tpart[8 * B_SZ];                 // per-(jtile, sample) trace partials

// ---------------- GEMM tiling ----------------
#define BM 128
#define BN 128
#define BK 16

__device__ __forceinline__ void sts_tile(float (*dst)[BM], const float4* v, int tid) {
#pragma unroll
    for (int l = 0; l < 2; l++) {
        int f = tid * 2 + l;
        int r = f >> 2, kq = f & 3;
        dst[kq * 4 + 0][r] = v[l].x;
        dst[kq * 4 + 1][r] = v[l].y;
        dst[kq * 4 + 2][r] = v[l].z;
        dst[kq * 4 + 3][r] = v[l].w;
    }
}

__device__ __forceinline__ void sts_t1(float (*dst)[BM], const float* v, int tid) {
#pragma unroll
    for (int i = 0; i < 8; i++) {
        int e = tid + i * 256;
        dst[e >> 7][e & 127] = v[i];
    }
}

// MODE 0: C = tanh(A @ W^T + bias)                     (forward hidden layers)
// MODE 1: C(=U2) = (1-hs^2) .* (U1 @ W^T), U1 generated on the fly from A(=h1), W0
// MODE 2: trace partials from (1-hs^2) .* (A(=U2) @ W^T) dotted with W3 rows
template <int MODE>
__global__ void __launch_bounds__(256, 2)
gemm_kernel(const float* __restrict__ A, const float* __restrict__ W,
            const float* __restrict__ bias, const float* __restrict__ hs,
            const float* __restrict__ W0p, const float* __restrict__ W3p,
            float* __restrict__ C)
{
    __shared__ float As[2][BK][BM];
    __shared__ float Bs[2][BK][BN];
    __shared__ float red[256];

    const int tid = threadIdx.x;
    const int tx = tid & 15, ty = tid >> 4;
    const int rowBase = blockIdx.y * BM;
    const int colBase = blockIdx.x * BN;

    float acc[8][8];
#pragma unroll
    for (int i = 0; i < 8; i++)
#pragma unroll
        for (int j = 0; j < 8; j++) acc[i][j] = 0.0f;

    // ---- prologue: load k-tile 0 into smem buffer 0 ----
    {
        float4 pb[2];
        if (MODE == 1) {
            float pt[8];
#pragma unroll
            for (int i = 0; i < 8; i++) {
                int e = tid + i * 256;
                int r = e & 127, kk = e >> 7;
                int grow = rowBase + r;
                float h = A[(size_t)(grow >> 5) * H_SZ + kk];
                pt[i] = (1.0f - h * h) * W0p[kk * 33 + (grow & 31)];
            }
            sts_t1(As[0], pt, tid);
        } else {
            float4 pa[2];
#pragma unroll
            for (int l = 0; l < 2; l++) {
                int f = tid * 2 + l;
                int r = f >> 2, kq = f & 3;
                pa[l] = *reinterpret_cast<const float4*>(A + (size_t)(rowBase + r) * K_SZ + kq * 4);
            }
            sts_tile(As[0], pa, tid);
        }
#pragma unroll
        for (int l = 0; l < 2; l++) {
            int f = tid * 2 + l;
            int r = f >> 2, kq = f & 3;
            pb[l] = *reinterpret_cast<const float4*>(W + (size_t)(colBase + r) * K_SZ + kq * 4);
        }
        sts_tile(Bs[0], pb, tid);
    }
    __syncthreads();

    // ---- main loop: double-buffered over 64 k-tiles ----
    const int NKT = K_SZ / BK;
    int cur = 0;
    for (int kt = 0; kt < NKT; kt++) {
        float4 na[2];
        float  nt[8];
        float4 nb[2];
        if (kt + 1 < NKT) {
            const int k0 = (kt + 1) * BK;
            if (MODE == 1) {
#pragma unroll
                for (int i = 0; i < 8; i++) {
                    int e = tid + i * 256;
                    int r = e & 127, kk = e >> 7;
                    int gk = k0 + kk;
                    int grow = rowBase + r;
                    float h = A[(size_t)(grow >> 5) * H_SZ + gk];
                    nt[i] = (1.0f - h * h) * W0p[gk * 33 + (grow & 31)];
                }
            } else {
#pragma unroll
                for (int l = 0; l < 2; l++) {
                    int f = tid * 2 + l;
                    int r = f >> 2, kq = f & 3;
                    na[l] = *reinterpret_cast<const float4*>(A + (size_t)(rowBase + r) * K_SZ + k0 + kq * 4);
                }
            }
#pragma unroll
            for (int l = 0; l < 2; l++) {
                int f = tid * 2 + l;
                int r = f >> 2, kq = f & 3;
                nb[l] = *reinterpret_cast<const float4*>(W + (size_t)(colBase + r) * K_SZ + k0 + kq * 4);
            }
        }

#pragma unroll
        for (int k = 0; k < BK; k++) {
            float av[8], bv[8];
            *reinterpret_cast<float4*>(&av[0]) = *reinterpret_cast<const float4*>(&As[cur][k][ty * 8]);
            *reinterpret_cast<float4*>(&av[4]) = *reinterpret_cast<const float4*>(&As[cur][k][ty * 8 + 4]);
            *reinterpret_cast<float4*>(&bv[0]) = *reinterpret_cast<const float4*>(&Bs[cur][k][tx * 8]);
            *reinterpret_cast<float4*>(&bv[4]) = *reinterpret_cast<const float4*>(&Bs[cur][k][tx * 8 + 4]);
#pragma unroll
            for (int i = 0; i < 8; i++)
#pragma unroll
                for (int j = 0; j < 8; j++)
                    acc[i][j] = fmaf(av[i], bv[j], acc[i][j]);
        }

        if (kt + 1 < NKT) {
            int nxt = cur ^ 1;
            if (MODE == 1) sts_t1(As[nxt], nt, tid);
            else           sts_tile(As[nxt], na, tid);
            sts_tile(Bs[nxt], nb, tid);
            __syncthreads();
            cur = nxt;
        }
    }

    // ---- epilogues ----
    if (MODE == 0) {
        const int c = colBase + tx * 8;
#pragma unroll
        for (int i = 0; i < 8; i++) {
            int r = rowBase + ty * 8 + i;
            float4 o0, o1;
            o0.x = tanhf(acc[i][0] + bias[c + 0]);
            o0.y = tanhf(acc[i][1] + bias[c + 1]);
            o0.z = tanhf(acc[i][2] + bias[c + 2]);
            o0.w = tanhf(acc[i][3] + bias[c + 3]);
            o1.x = tanhf(acc[i][4] + bias[c + 4]);
            o1.y = tanhf(acc[i][5] + bias[c + 5]);
            o1.z = tanhf(acc[i][6] + bias[c + 6]);
            o1.w = tanhf(acc[i][7] + bias[c + 7]);
            *reinterpret_cast<float4*>(C + (size_t)r * H_SZ + c)     = o0;
            *reinterpret_cast<float4*>(C + (size_t)r * H_SZ + c + 4) = o1;
        }
    } else if (MODE == 1) {
        const int bglob = (rowBase >> 5) + (ty >> 2);  // all 8 rows of this thread share one sample
        const int c = colBase + tx * 8;
        float sv[8];
#pragma unroll
        for (int j = 0; j < 8; j++) {
            float h = hs[(size_t)bglob * H_SZ + c + j];
            sv[j] = 1.0f - h * h;
        }
#pragma unroll
        for (int i = 0; i < 8; i++) {
            int r = rowBase + ty * 8 + i;
            float4 o0, o1;
            o0.x = acc[i][0] * sv[0];
            o0.y = acc[i][1] * sv[1];
            o0.z = acc[i][2] * sv[2];
            o0.w = acc[i][3] * sv[3];
            o1.x = acc[i][4] * sv[4];
            o1.y = acc[i][5] * sv[5];
            o1.z = acc[i][6] * sv[6];
            o1.w = acc[i][7] * sv[7];
            size_t base = (size_t)r * H_SZ + c;
            *reinterpret_cast<float4*>(C + base)     = o0;
            *reinterpret_cast<float4*>(C + base + 4) = o1;
        }
    } else {
        const int bglob = (rowBase >> 5) + (ty >> 2);
        float part = 0.0f;
#pragma unroll
        for (int j = 0; j < 8; j++) {
            int c = colBase + tx * 8 + j;
            float h = hs[(size_t)bglob * H_SZ + c];
            float s = 1.0f - h * h;
#pragma unroll
            for (int i = 0; i < 8; i++) {
                int d = (ty * 8 + i) & 31;
                part += W3p[d * H_SZ + c] * (acc[i][j] * s);
            }
        }
        red[tid] = part;
        __syncthreads();
        if (tid < 4) {
            float ssum = 0.0f;
#pragma unroll 8
            for (int t = 0; t < 64; t++) ssum += red[tid * 64 + t];
            // unique (jtile, sample) slot -> deterministic, no atomics
            g_tpart[blockIdx.x * B_SZ + (rowBase >> 5) + tid] = ssum;
        }
    }
}

// ---------------- small kernels ----------------

// h1 = tanh([z|t] @ W0^T + b0)
__global__ void layer0_kernel(const float* __restrict__ t, const float* __restrict__ z,
                              const float* __restrict__ W0, const float* __restrict__ b0,
                              float* __restrict__ h1)
{
    int idx = blockIdx.x * blockDim.x + threadIdx.x;   // B*H
    int j = idx & (H_SZ - 1);
    int b = idx >> 10;
    const float* w  = W0 + j * 33;
    const float* zr = z + b * D_SZ;
    float acc = b0[j] + t[0] * w[32];
#pragma unroll
    for (int d = 0; d < 32; d++) acc = fmaf(zr[d], w[d], acc);
    h1[idx] = tanhf(acc);
}

// out = h3 @ W3^T + b3
__global__ void out_kernel(const float* __restrict__ h3, const float* __restrict__ W3,
                           const float* __restrict__ b3, float* __restrict__ out)
{
    int idx = blockIdx.x * blockDim.x + threadIdx.x;   // B*D
    int d = idx & 31;
    int b = idx >> 5;
    const float* h = h3 + (size_t)b * H_SZ;
    const float* w = W3 + (size_t)d * H_SZ;
    float acc = 0.0f;
#pragma unroll 8
    for (int k = 0; k < H_SZ; k++) acc = fmaf(h[k], w[k], acc);
    out[idx] = acc + b3[d];
}

// divv[b] = -(sum of 8 j-tile partials)
__global__ void fin_kernel(float* __restrict__ out)
{
    int b = blockIdx.x * blockDim.x + threadIdx.x;
    if (b < B_SZ) {
        float s = 0.0f;
#pragma unroll
        for (int x = 0; x < 8; x++) s += g_tpart[x * B_SZ + b];
        out[B_SZ * D_SZ + b] = -s;
    }
}

// ---------------- launch ----------------
extern "C" void kernel_launch(void* const* d_in, const int* in_sizes, int n_in,
                              void* d_out, int out_size)
{
    const float* t  = (const float*)d_in[0];
    const float* z  = (const float*)d_in[1];
    const float* W0 = (const float*)d_in[2];
    const float* b0 = (const float*)d_in[3];
    const float* W1 = (const float*)d_in[4];
    const float* b1 = (const float*)d_in[5];
    const float* W2 = (const float*)d_in[6];
    const float* b2 = (const float*)d_in[7];
    const float* W3 = (const float*)d_in[8];
    const float* b3 = (const float*)d_in[9];
    float* out = (float*)d_out;

    float *ph1, *ph2, *ph3, *pU2;
    cudaGetSymbolAddress((void**)&ph1, g_h1);
    cudaGetSymbolAddress((void**)&ph2, g_h2);
    cudaGetSymbolAddress((void**)&ph3, g_h3);
    cudaGetSymbolAddress((void**)&pU2, g_U2);

    // forward
    layer0_kernel<<<(B_SZ * H_SZ) / 256, 256>>>(t, z, W0, b0, ph1);
    dim3 gF(H_SZ / BN, B_SZ / BM);           // (8, 32)
    gemm_kernel<0><<<gF, 256>>>(ph1, W1, b1, nullptr, nullptr, nullptr, ph2);
    gemm_kernel<0><<<gF, 256>>>(ph2, W2, b2, nullptr, nullptr, nullptr, ph3);
    out_kernel<<<(B_SZ * D_SZ) / 256, 256>>>(ph3, W3, b3, out);

    // tangent (JVP) chain: U2 = (1-h2^2) .* ((a1 .* W0') @ W1^T); trace from W2/W3
    dim3 gT(H_SZ / BN, MT / BM);             // (8, 1024)
    gemm_kernel<1><<<gT, 256>>>(ph1, W1, nullptr, ph2, W0, nullptr, pU2);
    gemm_kernel<2><<<gT, 256>>>(pU2, W2, nullptr, ph3, nullptr, W3, nullptr);

    fin_kernel<<<(B_SZ + 255) / 256, 256>>>(out);
}

// round 12
// speedup vs baseline: 1.9569x; 1.9493x over previous
#include <cuda_runtime.h>
#include <cuda_bf16.h>
#include <math.h>
#include <stdint.h>

#define B_SZ 4096
#define D_SZ 32
#define H_SZ 1024
#define MT   (B_SZ * D_SZ)   /* 131072 tangent rows (b,d) */

// ---------------- scratch (static device globals; no allocs) ----------------
__device__ float g_h1[B_SZ * H_SZ];
__device__ float g_h2[B_SZ * H_SZ];
__device__ float g_h3[B_SZ * H_SZ];
__device__ float g_U2[(size_t)MT * H_SZ];           // 512 MB
__device__ float g_tpart[8 * B_SZ];

// =====================================================================
// helpers
// =====================================================================
__device__ __forceinline__ uint32_t smem_u32_of(const void* p) {
    uint32_t a;
    asm("{ .reg .u64 t; cvta.to.shared.u64 t, %1; cvt.u32.u64 %0, t; }" : "=r"(a) : "l"(p));
    return a;
}

__device__ __forceinline__ void ldsm4(uint32_t r[4], uint32_t addr) {
    asm volatile("ldmatrix.sync.aligned.m8n8.x4.shared.b16 {%0,%1,%2,%3}, [%4];"
                 : "=r"(r[0]), "=r"(r[1]), "=r"(r[2]), "=r"(r[3]) : "r"(addr));
}

__device__ __forceinline__ void mma16816(float c[4], const uint32_t a[4],
                                         uint32_t b0, uint32_t b1) {
    asm volatile("mma.sync.aligned.m16n8k16.row.col.f32.bf16.bf16.f32 "
                 "{%0,%1,%2,%3}, {%4,%5,%6,%7}, {%8,%9}, {%0,%1,%2,%3};"
                 : "+f"(c[0]), "+f"(c[1]), "+f"(c[2]), "+f"(c[3])
                 : "r"(a[0]), "r"(a[1]), "r"(a[2]), "r"(a[3]), "r"(b0), "r"(b1));
}

// split x,y into bf16 hi/lo planes, packed bf16x2 (low half = first element)
__device__ __forceinline__ void bsplit2(float x, float y, uint32_t& hi, uint32_t& lo) {
    __nv_bfloat16 hx = __float2bfloat16_rn(x);
    __nv_bfloat16 hy = __float2bfloat16_rn(y);
    __nv_bfloat16 lx = __float2bfloat16_rn(x - __bfloat162float(hx));
    __nv_bfloat16 ly = __float2bfloat16_rn(y - __bfloat162float(hy));
    hi = (uint32_t)__bfloat16_as_ushort(hx) | ((uint32_t)__bfloat16_as_ushort(hy) << 16);
    lo = (uint32_t)__bfloat16_as_ushort(lx) | ((uint32_t)__bfloat16_as_ushort(ly) << 16);
}

// =====================================================================
// bf16-split mma.sync GEMM  (C = A @ W^T over K=1024)
//   MODE 0: C = tanh(A @ W^T + bias)                          (forward layers)
//   MODE 1: A built on the fly: U1[(b,d),k] = (1-h1[b,k]^2)*W0[k,d]
//           epilogue: C(=U2) = (1-h2^2) .* acc
//   MODE 2: trace partials: sum_{d,j} W3[d,j]*(1-h3[b,j]^2)*acc[(b,d),j]
// Block 128x128, warp 64x32 (8 warps), k-tile 32, double buffered.
// smem planes per buffer: A_hi, A_lo, B_hi, B_lo; row pitch 80 B (conflict-free
// ldmatrix: 80*r mod 128 cycles through all eight 16B phases).
// =====================================================================
#define PLANE 10240          /* 128 rows * 80 B */
#define SBUF  (4 * PLANE)    /* 4 planes per buffer */
#define SMEM_TOT (2 * SBUF)  /* 81920 B */

template <int MODE>
__global__ void __launch_bounds__(256, 1)
mma_gemm(const float* __restrict__ A, const float* __restrict__ W,
         const float* __restrict__ bias, const float* __restrict__ hs,
         const float* __restrict__ W0p, const float* __restrict__ W3p,
         float* __restrict__ C)
{
    extern __shared__ char sm[];
    __shared__ float red[4][4];
    const uint32_t sb = smem_u32_of(sm);
    const int tid = threadIdx.x, lane = tid & 31, wid = tid >> 5;
    const int warpM = wid >> 2, warpN = wid & 3;
    const int wr = warpM * 64, wn = warpN * 32;
    const int rowBase = blockIdx.y * 128, colBase = blockIdx.x * 128;

    float acc[4][4][4];
#pragma unroll
    for (int a = 0; a < 4; a++)
#pragma unroll
        for (int b = 0; b < 4; b++)
#pragma unroll
            for (int c = 0; c < 4; c++) acc[a][b][c] = 0.0f;

    // lane-derived ldmatrix addressing
    const int aRow = wr + (lane & 15);
    const int aChk = lane >> 4;                       // +ks*2
    const int bRowOff = ((lane >> 4) << 3) + (lane & 7);
    const int bChk = (lane >> 3) & 1;                 // +ks*2

    float4 va[4], vb[4];

    auto LDG = [&](int kt) {
        const int kb = kt * 32;
#pragma unroll
        for (int i = 0; i < 4; i++) {
            int q = tid + i * 256;
            int r = q >> 3, kq = q & 7, k0 = kb + kq * 4;
            if (MODE == 1) {
                int gr = rowBase + r, b = gr >> 5, d = gr & 31;
                float4 h = *reinterpret_cast<const float4*>(A + (size_t)b * H_SZ + k0);
                va[i].x = (1.0f - h.x * h.x) * W0p[(k0 + 0) * 33 + d];
                va[i].y = (1.0f - h.y * h.y) * W0p[(k0 + 1) * 33 + d];
                va[i].z = (1.0f - h.z * h.z) * W0p[(k0 + 2) * 33 + d];
                va[i].w = (1.0f - h.w * h.w) * W0p[(k0 + 3) * 33 + d];
            } else {
                va[i] = *reinterpret_cast<const float4*>(A + (size_t)(rowBase + r) * H_SZ + k0);
            }
            vb[i] = *reinterpret_cast<const float4*>(W + (size_t)(colBase + r) * H_SZ + k0);
        }
    };

    auto STS = [&](int s) {
#pragma unroll
        for (int i = 0; i < 4; i++) {
            int q = tid + i * 256;
            int r = q >> 3, kq = q & 7;
            uint32_t off = (uint32_t)(r * 80 + (kq >> 1) * 16 + (kq & 1) * 8);
            uint32_t h0, l0, h1, l1;
            bsplit2(va[i].x, va[i].y, h0, l0);
            bsplit2(va[i].z, va[i].w, h1, l1);
            *reinterpret_cast<uint2*>(sm + s * SBUF + off)             = make_uint2(h0, h1);
            *reinterpret_cast<uint2*>(sm + s * SBUF + PLANE + off)     = make_uint2(l0, l1);
            bsplit2(vb[i].x, vb[i].y, h0, l0);
            bsplit2(vb[i].z, vb[i].w, h1, l1);
            *reinterpret_cast<uint2*>(sm + s * SBUF + 2 * PLANE + off) = make_uint2(h0, h1);
            *reinterpret_cast<uint2*>(sm + s * SBUF + 3 * PLANE + off) = make_uint2(l0, l1);
        }
    };

    LDG(0);
    STS(0);
    __syncthreads();

    int cur = 0;
    for (int kt = 0; kt < 32; kt++) {
        if (kt + 1 < 32) LDG(kt + 1);

#pragma unroll
        for (int ks = 0; ks < 2; ks++) {
            uint32_t ah[4][4], al[4][4], bh[2][4], bl[2][4];
            const uint32_t base = sb + cur * SBUF;
#pragma unroll
            for (int mi = 0; mi < 4; mi++) {
                uint32_t ad = base + (uint32_t)((aRow + mi * 16) * 80 + (aChk + ks * 2) * 16);
                ldsm4(ah[mi], ad);
                ldsm4(al[mi], ad + PLANE);
            }
#pragma unroll
            for (int pr = 0; pr < 2; pr++) {
                uint32_t bd = base + 2 * PLANE +
                              (uint32_t)((wn + pr * 16 + bRowOff) * 80 + (bChk + ks * 2) * 16);
                ldsm4(bh[pr], bd);
                ldsm4(bl[pr], bd + PLANE);
            }
#pragma unroll
            for (int mi = 0; mi < 4; mi++)
#pragma unroll
                for (int ni = 0; ni < 4; ni++) {
                    const int pr = ni >> 1, o = (ni & 1) * 2;
                    mma16816(acc[mi][ni], ah[mi], bh[pr][o], bh[pr][o + 1]);
                    mma16816(acc[mi][ni], ah[mi], bl[pr][o], bl[pr][o + 1]);
                    mma16816(acc[mi][ni], al[mi], bh[pr][o], bh[pr][o + 1]);
                }
        }

        if (kt + 1 < 32) {
            int nxt = cur ^ 1;
            STS(nxt);
            __syncthreads();
            cur = nxt;
        }
    }

    // ---- epilogues ----
    const int l4 = lane >> 2, l2 = (lane & 3) * 2;

    if (MODE == 0 || MODE == 1) {
#pragma unroll
        for (int mi = 0; mi < 4; mi++) {
            int r0 = rowBase + wr + mi * 16 + l4;
#pragma unroll
            for (int ni = 0; ni < 4; ni++) {
                int c = colBase + wn + ni * 8 + l2;
                if (MODE == 0) {
                    float2 bb = *reinterpret_cast<const float2*>(bias + c);
                    float2 o0 = make_float2(tanhf(acc[mi][ni][0] + bb.x),
                                            tanhf(acc[mi][ni][1] + bb.y));
                    float2 o1 = make_float2(tanhf(acc[mi][ni][2] + bb.x),
                                            tanhf(acc[mi][ni][3] + bb.y));
                    *reinterpret_cast<float2*>(C + (size_t)r0 * H_SZ + c)       = o0;
                    *reinterpret_cast<float2*>(C + (size_t)(r0 + 8) * H_SZ + c) = o1;
                } else {
                    int b = r0 >> 5;
                    float2 h = *reinterpret_cast<const float2*>(hs + (size_t)b * H_SZ + c);
                    float s0 = 1.0f - h.x * h.x, s1 = 1.0f - h.y * h.y;
                    *reinterpret_cast<float2*>(C + (size_t)r0 * H_SZ + c) =
                        make_float2(acc[mi][ni][0] * s0, acc[mi][ni][1] * s1);
                    *reinterpret_cast<float2*>(C + (size_t)(r0 + 8) * H_SZ + c) =
                        make_float2(acc[mi][ni][2] * s0, acc[mi][ni][3] * s1);
                }
            }
        }
    } else {
        float p[2] = {0.0f, 0.0f};
#pragma unroll
        for (int mi = 0; mi < 4; mi++) {
            int r0 = rowBase + wr + mi * 16 + l4;
            int b = r0 >> 5, d0 = r0 & 31;    // r0 and r0+8 stay in the same sample
#pragma unroll
            for (int ni = 0; ni < 4; ni++) {
                int c = colBase + wn + ni * 8 + l2;
                float2 h  = *reinterpret_cast<const float2*>(hs + (size_t)b * H_SZ + c);
                float s0 = 1.0f - h.x * h.x, s1 = 1.0f - h.y * h.y;
                float2 w0 = *reinterpret_cast<const float2*>(W3p + (size_t)d0 * H_SZ + c);
                float2 w1 = *reinterpret_cast<const float2*>(W3p + (size_t)(d0 + 8) * H_SZ + c);
                p[mi >> 1] += acc[mi][ni][0] * s0 * w0.x + acc[mi][ni][1] * s1 * w0.y
                            + acc[mi][ni][2] * s0 * w1.x + acc[mi][ni][3] * s1 * w1.y;
            }
        }
#pragma unroll
        for (int j = 0; j < 2; j++) {
            float v = p[j];
#pragma unroll
            for (int o = 16; o > 0; o >>= 1) v += __shfl_xor_sync(0xffffffffu, v, o);
            if (lane == 0) red[warpM * 2 + j][warpN] = v;
        }
        __syncthreads();
        if (tid < 4) {
            float s = red[tid][0] + red[tid][1] + red[tid][2] + red[tid][3];
            g_tpart[blockIdx.x * B_SZ + (rowBase >> 5) + tid] = s;
        }
    }
}

// =====================================================================
// small kernels
// =====================================================================

// h1 = tanh([z|t] @ W0^T + b0)
__global__ void layer0_kernel(const float* __restrict__ t, const float* __restrict__ z,
                              const float* __restrict__ W0, const float* __restrict__ b0,
                              float* __restrict__ h1)
{
    int idx = blockIdx.x * blockDim.x + threadIdx.x;
    int j = idx & (H_SZ - 1);
    int b = idx >> 10;
    const float* w  = W0 + j * 33;
    const float* zr = z + b * D_SZ;
    float acc = b0[j] + t[0] * w[32];
#pragma unroll
    for (int d = 0; d < 32; d++) acc = fmaf(zr[d], w[d], acc);
    h1[idx] = tanhf(acc);
}

// out = h3 @ W3^T + b3 : one block per sample, warp-parallel dot products
__global__ void __launch_bounds__(256, 4)
out_kernel2(const float* __restrict__ h3, const float* __restrict__ W3,
            const float* __restrict__ b3, float* __restrict__ out)
{
    const int b = blockIdx.x;
    const int wid = threadIdx.x >> 5, lid = threadIdx.x & 31;
    const float* h = h3 + (size_t)b * H_SZ;
#pragma unroll
    for (int dd = 0; dd < 4; dd++) {
        const int d = wid * 4 + dd;
        const float* w = W3 + (size_t)d * H_SZ;
        float acc = 0.0f;
#pragma unroll 4
        for (int k = lid; k < H_SZ; k += 32) acc = fmaf(h[k], w[k], acc);
#pragma unroll
        for (int o = 16; o > 0; o >>= 1) acc += __shfl_xor_sync(0xffffffffu, acc, o);
        if (lid == 0) out[b * D_SZ + d] = acc + b3[d];
    }
}

// divv[b] = -(sum of 8 j-tile partials)
__global__ void fin_kernel(float* __restrict__ out)
{
    int b = blockIdx.x * blockDim.x + threadIdx.x;
    if (b < B_SZ) {
        float s = 0.0f;
#pragma unroll
        for (int x = 0; x < 8; x++) s += g_tpart[x * B_SZ + b];
        out[B_SZ * D_SZ + b] = -s;
    }
}

// ---------------- launch ----------------
extern "C" void kernel_launch(void* const* d_in, const int* in_sizes, int n_in,
                              void* d_out, int out_size)
{
    const float* t  = (const float*)d_in[0];
    const float* z  = (const float*)d_in[1];
    const float* W0 = (const float*)d_in[2];
    const float* b0 = (const float*)d_in[3];
    const float* W1 = (const float*)d_in[4];
    const float* b1 = (const float*)d_in[5];
    const float* W2 = (const float*)d_in[6];
    const float* b2 = (const float*)d_in[7];
    const float* W3 = (const float*)d_in[8];
    const float* b3 = (const float*)d_in[9];
    float* out = (float*)d_out;

    float *ph1, *ph2, *ph3, *pU2;
    cudaGetSymbolAddress((void**)&ph1, g_h1);
    cudaGetSymbolAddress((void**)&ph2, g_h2);
    cudaGetSymbolAddress((void**)&ph3, g_h3);
    cudaGetSymbolAddress((void**)&pU2, g_U2);

    cudaFuncSetAttribute(mma_gemm<0>, cudaFuncAttributeMaxDynamicSharedMemorySize, SMEM_TOT);
    cudaFuncSetAttribute(mma_gemm<1>, cudaFuncAttributeMaxDynamicSharedMemorySize, SMEM_TOT);
    cudaFuncSetAttribute(mma_gemm<2>, cudaFuncAttributeMaxDynamicSharedMemorySize, SMEM_TOT);

    // forward
    layer0_kernel<<<(B_SZ * H_SZ) / 256, 256>>>(t, z, W0, b0, ph1);
    dim3 gF(H_SZ / 128, B_SZ / 128);   // (8, 32)
    mma_gemm<0><<<gF, 256, SMEM_TOT>>>(ph1, W1, b1, nullptr, nullptr, nullptr, ph2);
    mma_gemm<0><<<gF, 256, SMEM_TOT>>>(ph2, W2, b2, nullptr, nullptr, nullptr, ph3);
    out_kernel2<<<B_SZ, 256>>>(ph3, W3, b3, out);

    // tangent chain (bf16-split-3 on tensor cores)
    dim3 gT(H_SZ / 128, MT / 128);     // (8, 1024)
    mma_gemm<1><<<gT, 256, SMEM_TOT>>>(ph1, W1, nullptr, ph2, W0, nullptr, pU2);
    mma_gemm<2><<<gT, 256, SMEM_TOT>>>(pU2, W2, nullptr, ph3, nullptr, W3, nullptr);

    fin_kernel<<<(B_SZ + 255) / 256, 256>>>(out);
}

// round 13
// speedup vs baseline: 2.1056x; 1.0760x over previous
#include <cuda_runtime.h>
#include <cuda_bf16.h>
#include <math.h>
#include <stdint.h>

#define B_SZ 4096
#define D_SZ 32
#define H_SZ 1024
#define MT   (B_SZ * D_SZ)   /* 131072 tangent rows (b,d) */

// ---------------- scratch (static device globals; no allocs) ----------------
__device__ float g_h1[B_SZ * H_SZ];
__device__ float g_h2[B_SZ * H_SZ];
__device__ float g_h3[B_SZ * H_SZ];
__device__ __nv_bfloat16 g_U1h[(size_t)MT * H_SZ];   // 256 MB
__device__ __nv_bfloat16 g_U1l[(size_t)MT * H_SZ];   // 256 MB
__device__ __nv_bfloat16 g_U2h[(size_t)MT * H_SZ];   // 256 MB
__device__ __nv_bfloat16 g_U2l[(size_t)MT * H_SZ];   // 256 MB
__device__ __nv_bfloat16 g_W1h[H_SZ * H_SZ], g_W1l[H_SZ * H_SZ];
__device__ __nv_bfloat16 g_W2h[H_SZ * H_SZ], g_W2l[H_SZ * H_SZ];
__device__ float g_tpart[8 * B_SZ];

// =====================================================================
// helpers
// =====================================================================
__device__ __forceinline__ uint32_t smem_u32_of(const void* p) {
    uint32_t a;
    asm("{ .reg .u64 t; cvta.to.shared.u64 t, %1; cvt.u32.u64 %0, t; }" : "=r"(a) : "l"(p));
    return a;
}
__device__ __forceinline__ void ldsm4(uint32_t r[4], uint32_t addr) {
    asm volatile("ldmatrix.sync.aligned.m8n8.x4.shared.b16 {%0,%1,%2,%3}, [%4];"
                 : "=r"(r[0]), "=r"(r[1]), "=r"(r[2]), "=r"(r[3]) : "r"(addr));
}
__device__ __forceinline__ void mma16816(float c[4], const uint32_t a[4],
                                         uint32_t b0, uint32_t b1) {
    asm volatile("mma.sync.aligned.m16n8k16.row.col.f32.bf16.bf16.f32 "
                 "{%0,%1,%2,%3}, {%4,%5,%6,%7}, {%8,%9}, {%0,%1,%2,%3};"
                 : "+f"(c[0]), "+f"(c[1]), "+f"(c[2]), "+f"(c[3])
                 : "r"(a[0]), "r"(a[1]), "r"(a[2]), "r"(a[3]), "r"(b0), "r"(b1));
}
__device__ __forceinline__ void bsplit2(float x, float y, uint32_t& hi, uint32_t& lo) {
    __nv_bfloat16 hx = __float2bfloat16_rn(x);
    __nv_bfloat16 hy = __float2bfloat16_rn(y);
    __nv_bfloat16 lx = __float2bfloat16_rn(x - __bfloat162float(hx));
    __nv_bfloat16 ly = __float2bfloat16_rn(y - __bfloat162float(hy));
    hi = (uint32_t)__bfloat16_as_ushort(hx) | ((uint32_t)__bfloat16_as_ushort(hy) << 16);
    lo = (uint32_t)__bfloat16_as_ushort(lx) | ((uint32_t)__bfloat16_as_ushort(ly) << 16);
}
__device__ __forceinline__ void cpa16(uint32_t dst, const void* src) {
    asm volatile("cp.async.cg.shared.global [%0], [%1], 16;" :: "r"(dst), "l"(src));
}
#define CP_COMMIT() asm volatile("cp.async.commit_group;" ::: "memory")
#define CP_WAIT1()  asm volatile("cp.async.wait_group 1;" ::: "memory")

// =====================================================================
// Tangent GEMM: pure bf16 pipeline (cp.async 3-stage -> ldmatrix -> HMMA)
//   C_acc = (Ah+Al) @ (Bh+Bl)^T  via 3-term split, K=1024, k-tile 32
//   MODE 1 epilogue: U2 = (1-h2^2).*acc, split -> U2h/U2l bf16
//   MODE 2 epilogue: trace partials sum_{d,j} W3[d,j]*(1-h3[b,j]^2)*acc
// Block 128x128, 8 warps (64x32 each). smem: 3 stages x 4 planes x 128x80B.
// =====================================================================
#define PLANE 10240
#define STAGE (4 * PLANE)
#define SMEM_TAN (3 * STAGE)   /* 122880 B */

template <int MODE>
__global__ void __launch_bounds__(256, 1)
tan_bf16(const __nv_bfloat16* __restrict__ Ah, const __nv_bfloat16* __restrict__ Al,
         const __nv_bfloat16* __restrict__ Bh, const __nv_bfloat16* __restrict__ Bl,
         const float* __restrict__ hs, const float* __restrict__ W3p,
         __nv_bfloat16* __restrict__ U2h, __nv_bfloat16* __restrict__ U2l)
{
    extern __shared__ char sm[];
    __shared__ float red[4][4];
    const uint32_t sb = smem_u32_of(sm);
    const int tid = threadIdx.x, lane = tid & 31, wid = tid >> 5;
    const int warpM = wid >> 2, warpN = wid & 3;
    const int wr = warpM * 64, wn = warpN * 32;
    const int rowBase = blockIdx.y * 128, colBase = blockIdx.x * 128;

    float acc[4][4][4];
#pragma unroll
    for (int a = 0; a < 4; a++)
#pragma unroll
        for (int b = 0; b < 4; b++)
#pragma unroll
            for (int c = 0; c < 4; c++) acc[a][b][c] = 0.0f;

    // this thread's two 16B chunks per plane: q = tid*2+l over 512 = 128 rows x 4 chunks
    const int r0c = (tid * 2) >> 2, kc0 = (tid * 2) & 3;
    const int r1c = (tid * 2 + 1) >> 2, kc1 = (tid * 2 + 1) & 3;

    auto ISSUE = [&](int kt) {
        const int st = kt % 3;
        const uint32_t s0 = sb + st * STAGE;
        const int kb = kt * 32;
        // chunk 0
        {
            const size_t ga = ((size_t)(rowBase + r0c) << 10) + kb + kc0 * 8;
            const size_t gb = ((size_t)(colBase + r0c) << 10) + kb + kc0 * 8;
            const uint32_t off = (uint32_t)(r0c * 80 + kc0 * 16);
            cpa16(s0 + off,             Ah + ga);
            cpa16(s0 + PLANE + off,     Al + ga);
            cpa16(s0 + 2 * PLANE + off, Bh + gb);
            cpa16(s0 + 3 * PLANE + off, Bl + gb);
        }
        // chunk 1
        {
            const size_t ga = ((size_t)(rowBase + r1c) << 10) + kb + kc1 * 8;
            const size_t gb = ((size_t)(colBase + r1c) << 10) + kb + kc1 * 8;
            const uint32_t off = (uint32_t)(r1c * 80 + kc1 * 16);
            cpa16(s0 + off,             Ah + ga);
            cpa16(s0 + PLANE + off,     Al + ga);
            cpa16(s0 + 2 * PLANE + off, Bh + gb);
            cpa16(s0 + 3 * PLANE + off, Bl + gb);
        }
        CP_COMMIT();
    };

    ISSUE(0);
    ISSUE(1);

    // lane-derived ldmatrix addressing (80B pitch, conflict-free)
    const int aRow = wr + (lane & 15);
    const int aChk = lane >> 4;
    const int bRowOff = ((lane >> 4) << 3) + (lane & 7);
    const int bChk = (lane >> 3) & 1;

    for (int kt = 0; kt < 32; kt++) {
        CP_WAIT1();
        __syncthreads();
        if (kt + 2 < 32) ISSUE(kt + 2);

        const uint32_t base = sb + (kt % 3) * STAGE;
#pragma unroll
        for (int ks = 0; ks < 2; ks++) {
            uint32_t ah[4][4], al[4][4], bh[2][4], bl[2][4];
#pragma unroll
            for (int mi = 0; mi < 4; mi++) {
                uint32_t ad = base + (uint32_t)((aRow + mi * 16) * 80 + (aChk + ks * 2) * 16);
                ldsm4(ah[mi], ad);
                ldsm4(al[mi], ad + PLANE);
            }
#pragma unroll
            for (int pr = 0; pr < 2; pr++) {
                uint32_t bd = base + 2 * PLANE +
                              (uint32_t)((wn + pr * 16 + bRowOff) * 80 + (bChk + ks * 2) * 16);
                ldsm4(bh[pr], bd);
                ldsm4(bl[pr], bd + PLANE);
            }
#pragma unroll
            for (int mi = 0; mi < 4; mi++)
#pragma unroll
                for (int ni = 0; ni < 4; ni++) {
                    const int pr = ni >> 1, o = (ni & 1) * 2;
                    mma16816(acc[mi][ni], ah[mi], bh[pr][o], bh[pr][o + 1]);
                    mma16816(acc[mi][ni], ah[mi], bl[pr][o], bl[pr][o + 1]);
                    mma16816(acc[mi][ni], al[mi], bh[pr][o], bh[pr][o + 1]);
                }
        }
        __syncthreads();
    }

    // ---- epilogues ----
    const int l4 = lane >> 2, l2 = (lane & 3) * 2;

    if (MODE == 1) {
#pragma unroll
        for (int mi = 0; mi < 4; mi++) {
            int r0 = rowBase + wr + mi * 16 + l4;
            int b = r0 >> 5;
#pragma unroll
            for (int ni = 0; ni < 4; ni++) {
                int c = colBase + wn + ni * 8 + l2;
                float2 h = *reinterpret_cast<const float2*>(hs + (size_t)b * H_SZ + c);
                float s0 = 1.0f - h.x * h.x, s1 = 1.0f - h.y * h.y;
                uint32_t hi, lo;
                bsplit2(acc[mi][ni][0] * s0, acc[mi][ni][1] * s1, hi, lo);
                *reinterpret_cast<uint32_t*>(U2h + (size_t)r0 * H_SZ + c) = hi;
                *reinterpret_cast<uint32_t*>(U2l + (size_t)r0 * H_SZ + c) = lo;
                bsplit2(acc[mi][ni][2] * s0, acc[mi][ni][3] * s1, hi, lo);
                *reinterpret_cast<uint32_t*>(U2h + (size_t)(r0 + 8) * H_SZ + c) = hi;
                *reinterpret_cast<uint32_t*>(U2l + (size_t)(r0 + 8) * H_SZ + c) = lo;
            }
        }
    } else {
        float p[2] = {0.0f, 0.0f};
#pragma unroll
        for (int mi = 0; mi < 4; mi++) {
            int r0 = rowBase + wr + mi * 16 + l4;
            int b = r0 >> 5, d0 = r0 & 31;
#pragma unroll
            for (int ni = 0; ni < 4; ni++) {
                int c = colBase + wn + ni * 8 + l2;
                float2 h  = *reinterpret_cast<const float2*>(hs + (size_t)b * H_SZ + c);
                float s0 = 1.0f - h.x * h.x, s1 = 1.0f - h.y * h.y;
                float2 w0 = *reinterpret_cast<const float2*>(W3p + (size_t)d0 * H_SZ + c);
                float2 w1 = *reinterpret_cast<const float2*>(W3p + (size_t)(d0 + 8) * H_SZ + c);
                p[mi >> 1] += acc[mi][ni][0] * s0 * w0.x + acc[mi][ni][1] * s1 * w0.y
                            + acc[mi][ni][2] * s0 * w1.x + acc[mi][ni][3] * s1 * w1.y;
            }
        }
#pragma unroll
        for (int j = 0; j < 2; j++) {
            float v = p[j];
#pragma unroll
            for (int o = 16; o > 0; o >>= 1) v += __shfl_xor_sync(0xffffffffu, v, o);
            if (lane == 0) red[warpM * 2 + j][warpN] = v;
        }
        __syncthreads();
        if (tid < 4) {
            float s = red[tid][0] + red[tid][1] + red[tid][2] + red[tid][3];
            g_tpart[blockIdx.x * B_SZ + (rowBase >> 5) + tid] = s;
        }
    }
}

// =====================================================================
// Forward GEMM (bf16-split mma.sync with inline conversion — small cost)
// =====================================================================
#define FPLANE 10240
#define FSBUF  (4 * FPLANE)
#define SMEM_FWD (2 * FSBUF)

__global__ void __launch_bounds__(256, 1)
fwd_gemm(const float* __restrict__ A, const float* __restrict__ W,
         const float* __restrict__ bias, float* __restrict__ C)
{
    extern __shared__ char sm[];
    const uint32_t sb = smem_u32_of(sm);
    const int tid = threadIdx.x, lane = tid & 31, wid = tid >> 5;
    const int warpM = wid >> 2, warpN = wid & 3;
    const int wr = warpM * 64, wn = warpN * 32;
    const int rowBase = blockIdx.y * 128, colBase = blockIdx.x * 128;

    float acc[4][4][4];
#pragma unroll
    for (int a = 0; a < 4; a++)
#pragma unroll
        for (int b = 0; b < 4; b++)
#pragma unroll
            for (int c = 0; c < 4; c++) acc[a][b][c] = 0.0f;

    const int aRow = wr + (lane & 15);
    const int aChk = lane >> 4;
    const int bRowOff = ((lane >> 4) << 3) + (lane & 7);
    const int bChk = (lane >> 3) & 1;

    float4 va[4], vb[4];
    auto LDG = [&](int kt) {
        const int kb = kt * 32;
#pragma unroll
        for (int i = 0; i < 4; i++) {
            int q = tid + i * 256;
            int r = q >> 3, kq = q & 7, k0 = kb + kq * 4;
            va[i] = *reinterpret_cast<const float4*>(A + (size_t)(rowBase + r) * H_SZ + k0);
            vb[i] = *reinterpret_cast<const float4*>(W + (size_t)(colBase + r) * H_SZ + k0);
        }
    };
    auto STS = [&](int s) {
#pragma unroll
        for (int i = 0; i < 4; i++) {
            int q = tid + i * 256;
            int r = q >> 3, kq = q & 7;
            uint32_t off = (uint32_t)(r * 80 + (kq >> 1) * 16 + (kq & 1) * 8);
            uint32_t h0, l0, h1, l1;
            bsplit2(va[i].x, va[i].y, h0, l0);
            bsplit2(va[i].z, va[i].w, h1, l1);
            *reinterpret_cast<uint2*>(sm + s * FSBUF + off)              = make_uint2(h0, h1);
            *reinterpret_cast<uint2*>(sm + s * FSBUF + FPLANE + off)     = make_uint2(l0, l1);
            bsplit2(vb[i].x, vb[i].y, h0, l0);
            bsplit2(vb[i].z, vb[i].w, h1, l1);
            *reinterpret_cast<uint2*>(sm + s * FSBUF + 2 * FPLANE + off) = make_uint2(h0, h1);
            *reinterpret_cast<uint2*>(sm + s * FSBUF + 3 * FPLANE + off) = make_uint2(l0, l1);
        }
    };

    LDG(0); STS(0);
    __syncthreads();

    int cur = 0;
    for (int kt = 0; kt < 32; kt++) {
        if (kt + 1 < 32) LDG(kt + 1);
        const uint32_t base = sb + cur * FSBUF;
#pragma unroll
        for (int ks = 0; ks < 2; ks++) {
            uint32_t ah[4][4], al[4][4], bh[2][4], bl[2][4];
#pragma unroll
            for (int mi = 0; mi < 4; mi++) {
                uint32_t ad = base + (uint32_t)((aRow + mi * 16) * 80 + (aChk + ks * 2) * 16);
                ldsm4(ah[mi], ad);
                ldsm4(al[mi], ad + FPLANE);
            }
#pragma unroll
            for (int pr = 0; pr < 2; pr++) {
                uint32_t bd = base + 2 * FPLANE +
                              (uint32_t)((wn + pr * 16 + bRowOff) * 80 + (bChk + ks * 2) * 16);
                ldsm4(bh[pr], bd);
                ldsm4(bl[pr], bd + FPLANE);
            }
#pragma unroll
            for (int mi = 0; mi < 4; mi++)
#pragma unroll
                for (int ni = 0; ni < 4; ni++) {
                    const int pr = ni >> 1, o = (ni & 1) * 2;
                    mma16816(acc[mi][ni], ah[mi], bh[pr][o], bh[pr][o + 1]);
                    mma16816(acc[mi][ni], ah[mi], bl[pr][o], bl[pr][o + 1]);
                    mma16816(acc[mi][ni], al[mi], bh[pr][o], bh[pr][o + 1]);
                }
        }
        if (kt + 1 < 32) {
            int nxt = cur ^ 1;
            STS(nxt);
            __syncthreads();
            cur = nxt;
        }
    }

    const int l4 = lane >> 2, l2 = (lane & 3) * 2;
#pragma unroll
    for (int mi = 0; mi < 4; mi++) {
        int r0 = rowBase + wr + mi * 16 + l4;
#pragma unroll
        for (int ni = 0; ni < 4; ni++) {
            int c = colBase + wn + ni * 8 + l2;
            float2 bb = *reinterpret_cast<const float2*>(bias + c);
            *reinterpret_cast<float2*>(C + (size_t)r0 * H_SZ + c) =
                make_float2(tanhf(acc[mi][ni][0] + bb.x), tanhf(acc[mi][ni][1] + bb.y));
            *reinterpret_cast<float2*>(C + (size_t)(r0 + 8) * H_SZ + c) =
                make_float2(tanhf(acc[mi][ni][2] + bb.x), tanhf(acc[mi][ni][3] + bb.y));
        }
    }
}

// =====================================================================
// prep kernels
// =====================================================================

// W fp32 [H,H] -> hi/lo bf16 planes
__global__ void conv_w(const float* __restrict__ W, __nv_bfloat16* __restrict__ Wh,
                       __nv_bfloat16* __restrict__ Wl)
{
    int i = blockIdx.x * blockDim.x + threadIdx.x;   // over H*H/4
    float4 v = reinterpret_cast<const float4*>(W)[i];
    uint32_t h0, l0, h1, l1;
    bsplit2(v.x, v.y, h0, l0);
    bsplit2(v.z, v.w, h1, l1);
    reinterpret_cast<uint2*>(Wh)[i] = make_uint2(h0, h1);
    reinterpret_cast<uint2*>(Wl)[i] = make_uint2(l0, l1);
}

// U1[(b,d),k] = (1-h1[b,k]^2) * W0[k,d]  -> hi/lo bf16 planes. One block per sample.
__global__ void __launch_bounds__(256)
prep_u1(const float* __restrict__ h1, const float* __restrict__ W0p,
        __nv_bfloat16* __restrict__ U1h, __nv_bfloat16* __restrict__ U1l)
{
    __shared__ float s1[H_SZ];
    const int b = blockIdx.x, tid = threadIdx.x;
    for (int k = tid; k < H_SZ; k += 256) {
        float h = h1[(size_t)b * H_SZ + k];
        s1[k] = 1.0f - h * h;
    }
    __syncthreads();
#pragma unroll 1
    for (int d = 0; d < 32; d++) {
        size_t rbase = ((size_t)(b * 32 + d)) << 10;
        for (int k2 = tid; k2 < H_SZ / 2; k2 += 256) {
            int k = k2 * 2;
            float u0 = s1[k] * W0p[k * 33 + d];
            float u1 = s1[k + 1] * W0p[(k + 1) * 33 + d];
            uint32_t hi, lo;
            bsplit2(u0, u1, hi, lo);
            *reinterpret_cast<uint32_t*>(U1h + rbase + k) = hi;
            *reinterpret_cast<uint32_t*>(U1l + rbase + k) = lo;
        }
    }
}

// h1 = tanh([z|t] @ W0^T + b0)
__global__ void layer0_kernel(const float* __restrict__ t, const float* __restrict__ z,
                              const float* __restrict__ W0, const float* __restrict__ b0,
                              float* __restrict__ h1)
{
    int idx = blockIdx.x * blockDim.x + threadIdx.x;
    int j = idx & (H_SZ - 1);
    int b = idx >> 10;
    const float* w  = W0 + j * 33;
    const float* zr = z + b * D_SZ;
    float acc = b0[j] + t[0] * w[32];
#pragma unroll
    for (int d = 0; d < 32; d++) acc = fmaf(zr[d], w[d], acc);
    h1[idx] = tanhf(acc);
}

// out = h3 @ W3^T + b3
__global__ void __launch_bounds__(256, 4)
out_kernel2(const float* __restrict__ h3, const float* __restrict__ W3,
            const float* __restrict__ b3, float* __restrict__ out)
{
    const int b = blockIdx.x;
    const int wid = threadIdx.x >> 5, lid = threadIdx.x & 31;
    const float* h = h3 + (size_t)b * H_SZ;
#pragma unroll
    for (int dd = 0; dd < 4; dd++) {
        const int d = wid * 4 + dd;
        const float* w = W3 + (size_t)d * H_SZ;
        float acc = 0.0f;
#pragma unroll 4
        for (int k = lid; k < H_SZ; k += 32) acc = fmaf(h[k], w[k], acc);
#pragma unroll
        for (int o = 16; o > 0; o >>= 1) acc += __shfl_xor_sync(0xffffffffu, acc, o);
        if (lid == 0) out[b * D_SZ + d] = acc + b3[d];
    }
}

// divv[b] = -(sum of 8 j-tile partials)
__global__ void fin_kernel(float* __restrict__ out)
{
    int b = blockIdx.x * blockDim.x + threadIdx.x;
    if (b < B_SZ) {
        float s = 0.0f;
#pragma unroll
        for (int x = 0; x < 8; x++) s += g_tpart[x * B_SZ + b];
        out[B_SZ * D_SZ + b] = -s;
    }
}

// ---------------- launch ----------------
extern "C" void kernel_launch(void* const* d_in, const int* in_sizes, int n_in,
                              void* d_out, int out_size)
{
    const float* t  = (const float*)d_in[0];
    const float* z  = (const float*)d_in[1];
    const float* W0 = (const float*)d_in[2];
    const float* b0 = (const float*)d_in[3];
    const float* W1 = (const float*)d_in[4];
    const float* b1 = (const float*)d_in[5];
    const float* W2 = (const float*)d_in[6];
    const float* b2 = (const float*)d_in[7];
    const float* W3 = (const float*)d_in[8];
    const float* b3 = (const float*)d_in[9];
    float* out = (float*)d_out;

    float *ph1, *ph2, *ph3;
    __nv_bfloat16 *pU1h, *pU1l, *pU2h, *pU2l, *pW1h, *pW1l, *pW2h, *pW2l;
    cudaGetSymbolAddress((void**)&ph1, g_h1);
    cudaGetSymbolAddress((void**)&ph2, g_h2);
    cudaGetSymbolAddress((void**)&ph3, g_h3);
    cudaGetSymbolAddress((void**)&pU1h, g_U1h);
    cudaGetSymbolAddress((void**)&pU1l, g_U1l);
    cudaGetSymbolAddress((void**)&pU2h, g_U2h);
    cudaGetSymbolAddress((void**)&pU2l, g_U2l);
    cudaGetSymbolAddress((void**)&pW1h, g_W1h);
    cudaGetSymbolAddress((void**)&pW1l, g_W1l);
    cudaGetSymbolAddress((void**)&pW2h, g_W2h);
    cudaGetSymbolAddress((void**)&pW2l, g_W2l);

    cudaFuncSetAttribute(fwd_gemm,    cudaFuncAttributeMaxDynamicSharedMemorySize, SMEM_FWD);
    cudaFuncSetAttribute(tan_bf16<1>, cudaFuncAttributeMaxDynamicSharedMemorySize, SMEM_TAN);
    cudaFuncSetAttribute(tan_bf16<2>, cudaFuncAttributeMaxDynamicSharedMemorySize, SMEM_TAN);

    // prep (independent of forward results except prep_u1 needs h1)
    layer0_kernel<<<(B_SZ * H_SZ) / 256, 256>>>(t, z, W0, b0, ph1);
    conv_w<<<(H_SZ * H_SZ / 4) / 256, 256>>>(W1, pW1h, pW1l);
    conv_w<<<(H_SZ * H_SZ / 4) / 256, 256>>>(W2, pW2h, pW2l);
    prep_u1<<<B_SZ, 256>>>(ph1, W0, pU1h, pU1l);

    // forward
    dim3 gF(H_SZ / 128, B_SZ / 128);   // (8, 32)
    fwd_gemm<<<gF, 256, SMEM_FWD>>>(ph1, W1, b1, ph2);
    fwd_gemm<<<gF, 256, SMEM_FWD>>>(ph2, W2, b2, ph3);
    out_kernel2<<<B_SZ, 256>>>(ph3, W3, b3, out);

    // tangent chain (pure-bf16 tensor-core pipeline)
    dim3 gT(H_SZ / 128, MT / 128);     // (8, 1024)
    tan_bf16<1><<<gT, 256, SMEM_TAN>>>(pU1h, pU1l, pW1h, pW1l, ph2, nullptr, pU2h, pU2l);
    tan_bf16<2><<<gT, 256, SMEM_TAN>>>(pU2h, pU2l, pW2h, pW2l, ph3, W3, nullptr, nullptr);

    fin_kernel<<<(B_SZ + 255) / 256, 256>>>(out);
}

// round 14
// speedup vs baseline: 2.1975x; 1.0436x over previous
#include <cuda_runtime.h>
#include <cuda_bf16.h>
#include <math.h>
#include <stdint.h>

#define B_SZ 4096
#define D_SZ 32
#define H_SZ 1024
#define MT   (B_SZ * D_SZ)   /* 131072 tangent rows (b,d) */

// ---------------- scratch (static device globals; no allocs) ----------------
__device__ float g_h1[B_SZ * H_SZ];
__device__ float g_h2[B_SZ * H_SZ];
__device__ float g_h3[B_SZ * H_SZ];
__device__ float g_W0T[D_SZ * H_SZ];                 // W0 transposed [d][k]
__device__ __nv_bfloat16 g_U1h[(size_t)MT * H_SZ];   // 256 MB
__device__ __nv_bfloat16 g_U1l[(size_t)MT * H_SZ];   // 256 MB
__device__ __nv_bfloat16 g_U2h[(size_t)MT * H_SZ];   // 256 MB
__device__ __nv_bfloat16 g_U2l[(size_t)MT * H_SZ];   // 256 MB
__device__ __nv_bfloat16 g_W1h[H_SZ * H_SZ], g_W1l[H_SZ * H_SZ];
__device__ __nv_bfloat16 g_W2h[H_SZ * H_SZ], g_W2l[H_SZ * H_SZ];
__device__ float g_tpart[8 * B_SZ];

// =====================================================================
// helpers
// =====================================================================
__device__ __forceinline__ uint32_t smem_u32_of(const void* p) {
    uint32_t a;
    asm("{ .reg .u64 t; cvta.to.shared.u64 t, %1; cvt.u32.u64 %0, t; }" : "=r"(a) : "l"(p));
    return a;
}
__device__ __forceinline__ void ldsm4(uint32_t r[4], uint32_t addr) {
    asm volatile("ldmatrix.sync.aligned.m8n8.x4.shared.b16 {%0,%1,%2,%3}, [%4];"
                 : "=r"(r[0]), "=r"(r[1]), "=r"(r[2]), "=r"(r[3]) : "r"(addr));
}
__device__ __forceinline__ void mma16816(float c[4], const uint32_t a[4],
                                         uint32_t b0, uint32_t b1) {
    asm volatile("mma.sync.aligned.m16n8k16.row.col.f32.bf16.bf16.f32 "
                 "{%0,%1,%2,%3}, {%4,%5,%6,%7}, {%8,%9}, {%0,%1,%2,%3};"
                 : "+f"(c[0]), "+f"(c[1]), "+f"(c[2]), "+f"(c[3])
                 : "r"(a[0]), "r"(a[1]), "r"(a[2]), "r"(a[3]), "r"(b0), "r"(b1));
}
__device__ __forceinline__ void bsplit2(float x, float y, uint32_t& hi, uint32_t& lo) {
    __nv_bfloat16 hx = __float2bfloat16_rn(x);
    __nv_bfloat16 hy = __float2bfloat16_rn(y);
    __nv_bfloat16 lx = __float2bfloat16_rn(x - __bfloat162float(hx));
    __nv_bfloat16 ly = __float2bfloat16_rn(y - __bfloat162float(hy));
    hi = (uint32_t)__bfloat16_as_ushort(hx) | ((uint32_t)__bfloat16_as_ushort(hy) << 16);
    lo = (uint32_t)__bfloat16_as_ushort(lx) | ((uint32_t)__bfloat16_as_ushort(ly) << 16);
}
__device__ __forceinline__ void cpa16(uint32_t dst, const void* src) {
    asm volatile("cp.async.cg.shared.global [%0], [%1], 16;" :: "r"(dst), "l"(src));
}
#define CP_COMMIT() asm volatile("cp.async.commit_group;" ::: "memory")
#define CP_WAIT0()  asm volatile("cp.async.wait_group 0;" ::: "memory")
#define CP_WAIT1()  asm volatile("cp.async.wait_group 1;" ::: "memory")
#define CP_WAIT2()  asm volatile("cp.async.wait_group 2;" ::: "memory")

// =====================================================================
// Tangent GEMM: pure bf16, 4-stage cp.async pipeline, ONE barrier per k-tile
//   C_acc = (Ah+Al) @ (Bh+Bl)^T  via 3-term split, K=1024, k-tile 32
//   MODE 1 epilogue: U2 = (1-h2^2).*acc, split -> U2h/U2l bf16
//   MODE 2 epilogue: trace partials sum_{d,j} W3[d,j]*(1-h3[b,j]^2)*acc
// Block 128x128, 8 warps (64x32 each). smem: 4 stages x 4 planes x 128x80B.
// Stage safety: ISSUE(kt+3) -> stage (kt+3)%4 = (kt-1)%4, whose reads finished
// in iter kt-1; the top-of-iter barrier of kt orders them. Single sync is safe.
// =====================================================================
#define PLANE 10240
#define STAGE (4 * PLANE)
#define SMEM_TAN (4 * STAGE)   /* 163840 B */

template <int MODE>
__global__ void __launch_bounds__(256, 1)
tan_bf16(const __nv_bfloat16* __restrict__ Ah, const __nv_bfloat16* __restrict__ Al,
         const __nv_bfloat16* __restrict__ Bh, const __nv_bfloat16* __restrict__ Bl,
         const float* __restrict__ hs, const float* __restrict__ W3p,
         __nv_bfloat16* __restrict__ U2h, __nv_bfloat16* __restrict__ U2l)
{
    extern __shared__ char sm[];
    __shared__ float red[4][4];
    const uint32_t sb = smem_u32_of(sm);
    const int tid = threadIdx.x, lane = tid & 31, wid = tid >> 5;
    const int warpM = wid >> 2, warpN = wid & 3;
    const int wr = warpM * 64, wn = warpN * 32;
    const int rowBase = blockIdx.y * 128, colBase = blockIdx.x * 128;

    float acc[4][4][4];
#pragma unroll
    for (int a = 0; a < 4; a++)
#pragma unroll
        for (int b = 0; b < 4; b++)
#pragma unroll
            for (int c = 0; c < 4; c++) acc[a][b][c] = 0.0f;

    // this thread's two 16B chunks per plane: q = tid*2+l over 512 = 128 rows x 4 chunks
    const int r0c = (tid * 2) >> 2, kc0 = (tid * 2) & 3;
    const int r1c = (tid * 2 + 1) >> 2, kc1 = (tid * 2 + 1) & 3;

    auto ISSUE = [&](int kt) {
        const uint32_t s0 = sb + (uint32_t)(kt & 3) * STAGE;
        const int kb = kt * 32;
        {
            const size_t ga = ((size_t)(rowBase + r0c) << 10) + kb + kc0 * 8;
            const size_t gb = ((size_t)(colBase + r0c) << 10) + kb + kc0 * 8;
            const uint32_t off = (uint32_t)(r0c * 80 + kc0 * 16);
            cpa16(s0 + off,             Ah + ga);
            cpa16(s0 + PLANE + off,     Al + ga);
            cpa16(s0 + 2 * PLANE + off, Bh + gb);
            cpa16(s0 + 3 * PLANE + off, Bl + gb);
        }
        {
            const size_t ga = ((size_t)(rowBase + r1c) << 10) + kb + kc1 * 8;
            const size_t gb = ((size_t)(colBase + r1c) << 10) + kb + kc1 * 8;
            const uint32_t off = (uint32_t)(r1c * 80 + kc1 * 16);
            cpa16(s0 + off,             Ah + ga);
            cpa16(s0 + PLANE + off,     Al + ga);
            cpa16(s0 + 2 * PLANE + off, Bh + gb);
            cpa16(s0 + 3 * PLANE + off, Bl + gb);
        }
        CP_COMMIT();
    };

    ISSUE(0);
    ISSUE(1);
    ISSUE(2);

    // lane-derived ldmatrix addressing (80B pitch, conflict-free)
    const int aRow = wr + (lane & 15);
    const int aChk = lane >> 4;
    const int bRowOff = ((lane >> 4) << 3) + (lane & 7);
    const int bChk = (lane >> 3) & 1;

    for (int kt = 0; kt < 32; kt++) {
        // exact tail waits: tiles issued so far end at min(kt+2, 31)
        if (kt < 30)      { CP_WAIT2(); }
        else if (kt == 30){ CP_WAIT1(); }
        else              { CP_WAIT0(); }
        __syncthreads();
        if (kt + 3 < 32) ISSUE(kt + 3);

        const uint32_t base = sb + (uint32_t)(kt & 3) * STAGE;
#pragma unroll
        for (int ks = 0; ks < 2; ks++) {
            uint32_t ah[4][4], al[4][4], bh[2][4], bl[2][4];
#pragma unroll
            for (int mi = 0; mi < 4; mi++) {
                uint32_t ad = base + (uint32_t)((aRow + mi * 16) * 80 + (aChk + ks * 2) * 16);
                ldsm4(ah[mi], ad);
                ldsm4(al[mi], ad + PLANE);
            }
#pragma unroll
            for (int pr = 0; pr < 2; pr++) {
                uint32_t bd = base + 2 * PLANE +
                              (uint32_t)((wn + pr * 16 + bRowOff) * 80 + (bChk + ks * 2) * 16);
                ldsm4(bh[pr], bd);
                ldsm4(bl[pr], bd + PLANE);
            }
#pragma unroll
            for (int mi = 0; mi < 4; mi++)
#pragma unroll
                for (int ni = 0; ni < 4; ni++) {
                    const int pr = ni >> 1, o = (ni & 1) * 2;
                    mma16816(acc[mi][ni], ah[mi], bh[pr][o], bh[pr][o + 1]);
                    mma16816(acc[mi][ni], ah[mi], bl[pr][o], bl[pr][o + 1]);
                    mma16816(acc[mi][ni], al[mi], bh[pr][o], bh[pr][o + 1]);
                }
        }
    }

    // ---- epilogues ----
    const int l4 = lane >> 2, l2 = (lane & 3) * 2;

    if (MODE == 1) {
#pragma unroll
        for (int mi = 0; mi < 4; mi++) {
            int r0 = rowBase + wr + mi * 16 + l4;
            int b = r0 >> 5;
#pragma unroll
            for (int ni = 0; ni < 4; ni++) {
                int c = colBase + wn + ni * 8 + l2;
                float2 h = *reinterpret_cast<const float2*>(hs + (size_t)b * H_SZ + c);
                float s0 = 1.0f - h.x * h.x, s1 = 1.0f - h.y * h.y;
                uint32_t hi, lo;
                bsplit2(acc[mi][ni][0] * s0, acc[mi][ni][1] * s1, hi, lo);
                *reinterpret_cast<uint32_t*>(U2h + (size_t)r0 * H_SZ + c) = hi;
                *reinterpret_cast<uint32_t*>(U2l + (size_t)r0 * H_SZ + c) = lo;
                bsplit2(acc[mi][ni][2] * s0, acc[mi][ni][3] * s1, hi, lo);
                *reinterpret_cast<uint32_t*>(U2h + (size_t)(r0 + 8) * H_SZ + c) = hi;
                *reinterpret_cast<uint32_t*>(U2l + (size_t)(r0 + 8) * H_SZ + c) = lo;
            }
        }
    } else {
        float p[2] = {0.0f, 0.0f};
#pragma unroll
        for (int mi = 0; mi < 4; mi++) {
            int r0 = rowBase + wr + mi * 16 + l4;
            int b = r0 >> 5, d0 = r0 & 31;
#pragma unroll
            for (int ni = 0; ni < 4; ni++) {
                int c = colBase + wn + ni * 8 + l2;
                float2 h  = *reinterpret_cast<const float2*>(hs + (size_t)b * H_SZ + c);
                float s0 = 1.0f - h.x * h.x, s1 = 1.0f - h.y * h.y;
                float2 w0 = *reinterpret_cast<const float2*>(W3p + (size_t)d0 * H_SZ + c);
                float2 w1 = *reinterpret_cast<const float2*>(W3p + (size_t)(d0 + 8) * H_SZ + c);
                p[mi >> 1] += acc[mi][ni][0] * s0 * w0.x + acc[mi][ni][1] * s1 * w0.y
                            + acc[mi][ni][2] * s0 * w1.x + acc[mi][ni][3] * s1 * w1.y;
            }
        }
#pragma unroll
        for (int j = 0; j < 2; j++) {
            float v = p[j];
#pragma unroll
            for (int o = 16; o > 0; o >>= 1) v += __shfl_xor_sync(0xffffffffu, v, o);
            if (lane == 0) red[warpM * 2 + j][warpN] = v;
        }
        __syncthreads();
        if (tid < 4) {
            float s = red[tid][0] + red[tid][1] + red[tid][2] + red[tid][3];
            g_tpart[blockIdx.x * B_SZ + (rowBase >> 5) + tid] = s;
        }
    }
}

// =====================================================================
// Forward GEMM (bf16-split mma.sync with inline conversion — small cost)
// =====================================================================
#define FPLANE 10240
#define FSBUF  (4 * FPLANE)
#define SMEM_FWD (2 * FSBUF)

__global__ void __launch_bounds__(256, 1)
fwd_gemm(const float* __restrict__ A, const float* __restrict__ W,
         const float* __restrict__ bias, float* __restrict__ C)
{
    extern __shared__ char sm[];
    const uint32_t sb = smem_u32_of(sm);
    const int tid = threadIdx.x, lane = tid & 31, wid = tid >> 5;
    const int warpM = wid >> 2, warpN = wid & 3;
    const int wr = warpM * 64, wn = warpN * 32;
    const int rowBase = blockIdx.y * 128, colBase = blockIdx.x * 128;

    float acc[4][4][4];
#pragma unroll
    for (int a = 0; a < 4; a++)
#pragma unroll
        for (int b = 0; b < 4; b++)
#pragma unroll
            for (int c = 0; c < 4; c++) acc[a][b][c] = 0.0f;

    const int aRow = wr + (lane & 15);
    const int aChk = lane >> 4;
    const int bRowOff = ((lane >> 4) << 3) + (lane & 7);
    const int bChk = (lane >> 3) & 1;

    float4 va[4], vb[4];
    auto LDG = [&](int kt) {
        const int kb = kt * 32;
#pragma unroll
        for (int i = 0; i < 4; i++) {
            int q = tid + i * 256;
            int r = q >> 3, kq = q & 7, k0 = kb + kq * 4;
            va[i] = *reinterpret_cast<const float4*>(A + (size_t)(rowBase + r) * H_SZ + k0);
            vb[i] = *reinterpret_cast<const float4*>(W + (size_t)(colBase + r) * H_SZ + k0);
        }
    };
    auto STS = [&](int s) {
#pragma unroll
        for (int i = 0; i < 4; i++) {
            int q = tid + i * 256;
            int r = q >> 3, kq = q & 7;
            uint32_t off = (uint32_t)(r * 80 + (kq >> 1) * 16 + (kq & 1) * 8);
            uint32_t h0, l0, h1, l1;
            bsplit2(va[i].x, va[i].y, h0, l0);
            bsplit2(va[i].z, va[i].w, h1, l1);
            *reinterpret_cast<uint2*>(sm + s * FSBUF + off)              = make_uint2(h0, h1);
            *reinterpret_cast<uint2*>(sm + s * FSBUF + FPLANE + off)     = make_uint2(l0, l1);
            bsplit2(vb[i].x, vb[i].y, h0, l0);
            bsplit2(vb[i].z, vb[i].w, h1, l1);
            *reinterpret_cast<uint2*>(sm + s * FSBUF + 2 * FPLANE + off) = make_uint2(h0, h1);
            *reinterpret_cast<uint2*>(sm + s * FSBUF + 3 * FPLANE + off) = make_uint2(l0, l1);
        }
    };

    LDG(0); STS(0);
    __syncthreads();

    int cur = 0;
    for (int kt = 0; kt < 32; kt++) {
        if (kt + 1 < 32) LDG(kt + 1);
        const uint32_t base = sb + cur * FSBUF;
#pragma unroll
        for (int ks = 0; ks < 2; ks++) {
            uint32_t ah[4][4], al[4][4], bh[2][4], bl[2][4];
#pragma unroll
            for (int mi = 0; mi < 4; mi++) {
                uint32_t ad = base + (uint32_t)((aRow + mi * 16) * 80 + (aChk + ks * 2) * 16);
                ldsm4(ah[mi], ad);
                ldsm4(al[mi], ad + FPLANE);
            }
#pragma unroll
            for (int pr = 0; pr < 2; pr++) {
                uint32_t bd = base + 2 * FPLANE +
                              (uint32_t)((wn + pr * 16 + bRowOff) * 80 + (bChk + ks * 2) * 16);
                ldsm4(bh[pr], bd);
                ldsm4(bl[pr], bd + FPLANE);
            }
#pragma unroll
            for (int mi = 0; mi < 4; mi++)
#pragma unroll
                for (int ni = 0; ni < 4; ni++) {
                    const int pr = ni >> 1, o = (ni & 1) * 2;
                    mma16816(acc[mi][ni], ah[mi], bh[pr][o], bh[pr][o + 1]);
                    mma16816(acc[mi][ni], ah[mi], bl[pr][o], bl[pr][o + 1]);
                    mma16816(acc[mi][ni], al[mi], bh[pr][o], bh[pr][o + 1]);
                }
        }
        if (kt + 1 < 32) {
            int nxt = cur ^ 1;
            STS(nxt);
            __syncthreads();
            cur = nxt;
        }
    }

    const int l4 = lane >> 2, l2 = (lane & 3) * 2;
#pragma unroll
    for (int mi = 0; mi < 4; mi++) {
        int r0 = rowBase + wr + mi * 16 + l4;
#pragma unroll
        for (int ni = 0; ni < 4; ni++) {
            int c = colBase + wn + ni * 8 + l2;
            float2 bb = *reinterpret_cast<const float2*>(bias + c);
            *reinterpret_cast<float2*>(C + (size_t)r0 * H_SZ + c) =
                make_float2(tanhf(acc[mi][ni][0] + bb.x), tanhf(acc[mi][ni][1] + bb.y));
            *reinterpret_cast<float2*>(C + (size_t)(r0 + 8) * H_SZ + c) =
                make_float2(tanhf(acc[mi][ni][2] + bb.x), tanhf(acc[mi][ni][3] + bb.y));
        }
    }
}

// =====================================================================
// prep kernels
// =====================================================================

// W fp32 [H,H] -> hi/lo bf16 planes
__global__ void conv_w(const float* __restrict__ W, __nv_bfloat16* __restrict__ Wh,
                       __nv_bfloat16* __restrict__ Wl)
{
    int i = blockIdx.x * blockDim.x + threadIdx.x;   // over H*H/4
    float4 v = reinterpret_cast<const float4*>(W)[i];
    uint32_t h0, l0, h1, l1;
    bsplit2(v.x, v.y, h0, l0);
    bsplit2(v.z, v.w, h1, l1);
    reinterpret_cast<uint2*>(Wh)[i] = make_uint2(h0, h1);
    reinterpret_cast<uint2*>(Wl)[i] = make_uint2(l0, l1);
}

// W0 [H,33] -> W0T [32][H] (one-shot, tiny)
__global__ void conv_w0t(const float* __restrict__ W0, float* __restrict__ W0T)
{
    int idx = blockIdx.x * blockDim.x + threadIdx.x;   // 32768
    int d = idx >> 10, k = idx & (H_SZ - 1);
    W0T[idx] = W0[k * 33 + d];
}

// U1[(b,d),k] = (1-h1[b,k]^2) * W0T[d,k] -> hi/lo bf16. Fully coalesced.
__global__ void __launch_bounds__(256)
prep_u1(const float* __restrict__ h1, const float* __restrict__ W0T,
        __nv_bfloat16* __restrict__ U1h, __nv_bfloat16* __restrict__ U1l)
{
    __shared__ float s1[H_SZ];
    const int b = blockIdx.x, tid = threadIdx.x;
    {
        float4 h = *reinterpret_cast<const float4*>(h1 + (size_t)b * H_SZ + tid * 4);
        s1[tid * 4 + 0] = 1.0f - h.x * h.x;
        s1[tid * 4 + 1] = 1.0f - h.y * h.y;
        s1[tid * 4 + 2] = 1.0f - h.z * h.z;
        s1[tid * 4 + 3] = 1.0f - h.w * h.w;
    }
    __syncthreads();
#pragma unroll 1
    for (int d = 0; d < 32; d++) {
        float4 w = *reinterpret_cast<const float4*>(W0T + d * H_SZ + tid * 4);
        float u0 = s1[tid * 4 + 0] * w.x;
        float u1 = s1[tid * 4 + 1] * w.y;
        float u2 = s1[tid * 4 + 2] * w.z;
        float u3 = s1[tid * 4 + 3] * w.w;
        uint32_t h0, l0, h1b, l1;
        bsplit2(u0, u1, h0, l0);
        bsplit2(u2, u3, h1b, l1);
        size_t base = ((size_t)(b * 32 + d) << 10) + tid * 4;
        *reinterpret_cast<uint2*>(U1h + base) = make_uint2(h0, h1b);
        *reinterpret_cast<uint2*>(U1l + base) = make_uint2(l0, l1);
    }
}

// h1 = tanh([z|t] @ W0^T + b0)
__global__ void layer0_kernel(const float* __restrict__ t, const float* __restrict__ z,
                              const float* __restrict__ W0, const float* __restrict__ b0,
                              float* __restrict__ h1)
{
    int idx = blockIdx.x * blockDim.x + threadIdx.x;
    int j = idx & (H_SZ - 1);
    int b = idx >> 10;
    const float* w  = W0 + j * 33;
    const float* zr = z + b * D_SZ;
    float acc = b0[j] + t[0] * w[32];
#pragma unroll
    for (int d = 0; d < 32; d++) acc = fmaf(zr[d], w[d], acc);
    h1[idx] = tanhf(acc);
}

// out = h3 @ W3^T + b3
__global__ void __launch_bounds__(256, 4)
out_kernel2(const float* __restrict__ h3, const float* __restrict__ W3,
            const float* __restrict__ b3, float* __restrict__ out)
{
    const int b = blockIdx.x;
    const int wid = threadIdx.x >> 5, lid = threadIdx.x & 31;
    const float* h = h3 + (size_t)b * H_SZ;
#pragma unroll
    for (int dd = 0; dd < 4; dd++) {
        const int d = wid * 4 + dd;
        const float* w = W3 + (size_t)d * H_SZ;
        float acc = 0.0f;
#pragma unroll 4
        for (int k = lid; k < H_SZ; k += 32) acc = fmaf(h[k], w[k], acc);
#pragma unroll
        for (int o = 16; o > 0; o >>= 1) acc += __shfl_xor_sync(0xffffffffu, acc, o);
        if (lid == 0) out[b * D_SZ + d] = acc + b3[d];
    }
}

// divv[b] = -(sum of 8 j-tile partials)
__global__ void fin_kernel(float* __restrict__ out)
{
    int b = blockIdx.x * blockDim.x + threadIdx.x;
    if (b < B_SZ) {
        float s = 0.0f;
#pragma unroll
        for (int x = 0; x < 8; x++) s += g_tpart[x * B_SZ + b];
        out[B_SZ * D_SZ + b] = -s;
    }
}

// ---------------- launch ----------------
extern "C" void kernel_launch(void* const* d_in, const int* in_sizes, int n_in,
                              void* d_out, int out_size)
{
    const float* t  = (const float*)d_in[0];
    const float* z  = (const float*)d_in[1];
    const float* W0 = (const float*)d_in[2];
    const float* b0 = (const float*)d_in[3];
    const float* W1 = (const float*)d_in[4];
    const float* b1 = (const float*)d_in[5];
    const float* W2 = (const float*)d_in[6];
    const float* b2 = (const float*)d_in[7];
    const float* W3 = (const float*)d_in[8];
    const float* b3 = (const float*)d_in[9];
    float* out = (float*)d_out;

    float *ph1, *ph2, *ph3, *pW0T;
    __nv_bfloat16 *pU1h, *pU1l, *pU2h, *pU2l, *pW1h, *pW1l, *pW2h, *pW2l;
    cudaGetSymbolAddress((void**)&ph1, g_h1);
    cudaGetSymbolAddress((void**)&ph2, g_h2);
    cudaGetSymbolAddress((void**)&ph3, g_h3);
    cudaGetSymbolAddress((void**)&pW0T, g_W0T);
    cudaGetSymbolAddress((void**)&pU1h, g_U1h);
    cudaGetSymbolAddress((void**)&pU1l, g_U1l);
    cudaGetSymbolAddress((void**)&pU2h, g_U2h);
    cudaGetSymbolAddress((void**)&pU2l, g_U2l);
    cudaGetSymbolAddress((void**)&pW1h, g_W1h);
    cudaGetSymbolAddress((void**)&pW1l, g_W1l);
    cudaGetSymbolAddress((void**)&pW2h, g_W2h);
    cudaGetSymbolAddress((void**)&pW2l, g_W2l);

    cudaFuncSetAttribute(fwd_gemm,    cudaFuncAttributeMaxDynamicSharedMemorySize, SMEM_FWD);
    cudaFuncSetAttribute(tan_bf16<1>, cudaFuncAttributeMaxDynamicSharedMemorySize, SMEM_TAN);
    cudaFuncSetAttribute(tan_bf16<2>, cudaFuncAttributeMaxDynamicSharedMemorySize, SMEM_TAN);

    // prep
    layer0_kernel<<<(B_SZ * H_SZ) / 256, 256>>>(t, z, W0, b0, ph1);
    conv_w0t<<<(D_SZ * H_SZ) / 256, 256>>>(W0, pW0T);
    conv_w<<<(H_SZ * H_SZ / 4) / 256, 256>>>(W1, pW1h, pW1l);
    conv_w<<<(H_SZ * H_SZ / 4) / 256, 256>>>(W2, pW2h, pW2l);
    prep_u1<<<B_SZ, 256>>>(ph1, pW0T, pU1h, pU1l);

    // forward
    dim3 gF(H_SZ / 128, B_SZ / 128);   // (8, 32)
    fwd_gemm<<<gF, 256, SMEM_FWD>>>(ph1, W1, b1, ph2);
    fwd_gemm<<<gF, 256, SMEM_FWD>>>(ph2, W2, b2, ph3);
    out_kernel2<<<B_SZ, 256>>>(ph3, W3, b3, out);

    // tangent chain (pure-bf16 tensor-core pipeline)
    dim3 gT(H_SZ / 128, MT / 128);     // (8, 1024)
    tan_bf16<1><<<gT, 256, SMEM_TAN>>>(pU1h, pU1l, pW1h, pW1l, ph2, nullptr, pU2h, pU2l);
    tan_bf16<2><<<gT, 256, SMEM_TAN>>>(pU2h, pU2l, pW2h, pW2l, ph3, W3, nullptr, nullptr);

    fin_kernel<<<(B_SZ + 255) / 256, 256>>>(out);
}

// round 15
// speedup vs baseline: 2.2004x; 1.0013x over previous
#include <cuda_runtime.h>
#include <cuda_bf16.h>
#include <math.h>
#include <stdint.h>

#define B_SZ 4096
#define D_SZ 32
#define H_SZ 1024
#define MT   (B_SZ * D_SZ)   /* 131072 tangent rows (b,d) */

// ---------------- scratch (static device globals; no allocs) ----------------
__device__ float g_h1[B_SZ * H_SZ];
__device__ float g_h2[B_SZ * H_SZ];
__device__ float g_h3[B_SZ * H_SZ];
__device__ float g_W0T[D_SZ * H_SZ];                 // W0 transposed [d][k]
__device__ __nv_bfloat16 g_U1h[(size_t)MT * H_SZ];   // 256 MB
__device__ __nv_bfloat16 g_U1l[(size_t)MT * H_SZ];   // 256 MB
__device__ __nv_bfloat16 g_U2h[(size_t)MT * H_SZ];   // 256 MB
__device__ __nv_bfloat16 g_U2l[(size_t)MT * H_SZ];   // 256 MB
__device__ __nv_bfloat16 g_W1h[H_SZ * H_SZ], g_W1l[H_SZ * H_SZ];
__device__ __nv_bfloat16 g_W2h[H_SZ * H_SZ], g_W2l[H_SZ * H_SZ];
__device__ float g_tpart[8 * B_SZ];

// =====================================================================
// helpers
// =====================================================================
__device__ __forceinline__ uint32_t smem_u32_of(const void* p) {
    uint32_t a;
    asm("{ .reg .u64 t; cvta.to.shared.u64 t, %1; cvt.u32.u64 %0, t; }" : "=r"(a) : "l"(p));
    return a;
}
__device__ __forceinline__ void ldsm4(uint32_t r[4], uint32_t addr) {
    asm volatile("ldmatrix.sync.aligned.m8n8.x4.shared.b16 {%0,%1,%2,%3}, [%4];"
                 : "=r"(r[0]), "=r"(r[1]), "=r"(r[2]), "=r"(r[3]) : "r"(addr));
}
__device__ __forceinline__ void mma16816(float c[4], const uint32_t a[4],
                                         uint32_t b0, uint32_t b1) {
    asm volatile("mma.sync.aligned.m16n8k16.row.col.f32.bf16.bf16.f32 "
                 "{%0,%1,%2,%3}, {%4,%5,%6,%7}, {%8,%9}, {%0,%1,%2,%3};"
                 : "+f"(c[0]), "+f"(c[1]), "+f"(c[2]), "+f"(c[3])
                 : "r"(a[0]), "r"(a[1]), "r"(a[2]), "r"(a[3]), "r"(b0), "r"(b1));
}
__device__ __forceinline__ void bsplit2(float x, float y, uint32_t& hi, uint32_t& lo) {
    __nv_bfloat16 hx = __float2bfloat16_rn(x);
    __nv_bfloat16 hy = __float2bfloat16_rn(y);
    __nv_bfloat16 lx = __float2bfloat16_rn(x - __bfloat162float(hx));
    __nv_bfloat16 ly = __float2bfloat16_rn(y - __bfloat162float(hy));
    hi = (uint32_t)__bfloat16_as_ushort(hx) | ((uint32_t)__bfloat16_as_ushort(hy) << 16);
    lo = (uint32_t)__bfloat16_as_ushort(lx) | ((uint32_t)__bfloat16_as_ushort(ly) << 16);
}
__device__ __forceinline__ void cpa16(uint32_t dst, const void* src) {
    asm volatile("cp.async.cg.shared.global [%0], [%1], 16;" :: "r"(dst), "l"(src));
}
#define CP_COMMIT() asm volatile("cp.async.commit_group;" ::: "memory")
#define CP_WAIT0()  asm volatile("cp.async.wait_group 0;" ::: "memory")
#define CP_WAIT1()  asm volatile("cp.async.wait_group 1;" ::: "memory")
#define CP_WAIT2()  asm volatile("cp.async.wait_group 2;" ::: "memory")

// =====================================================================
// Tangent GEMM: pure bf16, 4-stage cp.async pipeline, ONE barrier per k-tile
//   C_acc = (Ah+Al) @ (Bh+Bl)^T  via 3-term split, K=1024, k-tile 32
//   MODE 1 epilogue: U2 = (1-h2^2).*acc, split -> U2h/U2l bf16
//   MODE 2 epilogue: trace partials sum_{d,j} W3[d,j]*(1-h3[b,j]^2)*acc
// Block 128x128, 8 warps (64x32 each). smem: 4 stages x 4 planes x 128x80B.
// Stage safety: ISSUE(kt+3) -> stage (kt+3)%4 = (kt-1)%4, whose reads finished
// in iter kt-1; the top-of-iter barrier of kt orders them. Single sync is safe.
// =====================================================================
#define PLANE 10240
#define STAGE (4 * PLANE)
#define SMEM_TAN (4 * STAGE)   /* 163840 B */

template <int MODE>
__global__ void __launch_bounds__(256, 1)
tan_bf16(const __nv_bfloat16* __restrict__ Ah, const __nv_bfloat16* __restrict__ Al,
         const __nv_bfloat16* __restrict__ Bh, const __nv_bfloat16* __restrict__ Bl,
         const float* __restrict__ hs, const float* __restrict__ W3p,
         __nv_bfloat16* __restrict__ U2h, __nv_bfloat16* __restrict__ U2l)
{
    extern __shared__ char sm[];
    __shared__ float red[4][4];
    const uint32_t sb = smem_u32_of(sm);
    const int tid = threadIdx.x, lane = tid & 31, wid = tid >> 5;
    const int warpM = wid >> 2, warpN = wid & 3;
    const int wr = warpM * 64, wn = warpN * 32;
    const int rowBase = blockIdx.y * 128, colBase = blockIdx.x * 128;

    float acc[4][4][4];
#pragma unroll
    for (int a = 0; a < 4; a++)
#pragma unroll
        for (int b = 0; b < 4; b++)
#pragma unroll
            for (int c = 0; c < 4; c++) acc[a][b][c] = 0.0f;

    // this thread's two 16B chunks per plane: q = tid*2+l over 512 = 128 rows x 4 chunks
    const int r0c = (tid * 2) >> 2, kc0 = (tid * 2) & 3;
    const int r1c = (tid * 2 + 1) >> 2, kc1 = (tid * 2 + 1) & 3;

    auto ISSUE = [&](int kt) {
        const uint32_t s0 = sb + (uint32_t)(kt & 3) * STAGE;
        const int kb = kt * 32;
        {
            const size_t ga = ((size_t)(rowBase + r0c) << 10) + kb + kc0 * 8;
            const size_t gb = ((size_t)(colBase + r0c) << 10) + kb + kc0 * 8;
            const uint32_t off = (uint32_t)(r0c * 80 + kc0 * 16);
            cpa16(s0 + off,             Ah + ga);
            cpa16(s0 + PLANE + off,     Al + ga);
            cpa16(s0 + 2 * PLANE + off, Bh + gb);
            cpa16(s0 + 3 * PLANE + off, Bl + gb);
        }
        {
            const size_t ga = ((size_t)(rowBase + r1c) << 10) + kb + kc1 * 8;
            const size_t gb = ((size_t)(colBase + r1c) << 10) + kb + kc1 * 8;
            const uint32_t off = (uint32_t)(r1c * 80 + kc1 * 16);
            cpa16(s0 + off,             Ah + ga);
            cpa16(s0 + PLANE + off,     Al + ga);
            cpa16(s0 + 2 * PLANE + off, Bh + gb);
            cpa16(s0 + 3 * PLANE + off, Bl + gb);
        }
        CP_COMMIT();
    };

    ISSUE(0);
    ISSUE(1);
    ISSUE(2);

    // lane-derived ldmatrix addressing (80B pitch, conflict-free)
    const int aRow = wr + (lane & 15);
    const int aChk = lane >> 4;
    const int bRowOff = ((lane >> 4) << 3) + (lane & 7);
    const int bChk = (lane >> 3) & 1;

    for (int kt = 0; kt < 32; kt++) {
        // exact tail waits: tiles issued so far end at min(kt+2, 31)
        if (kt < 30)      { CP_WAIT2(); }
        else if (kt == 30){ CP_WAIT1(); }
        else              { CP_WAIT0(); }
        __syncthreads();
        if (kt + 3 < 32) ISSUE(kt + 3);

        const uint32_t base = sb + (uint32_t)(kt & 3) * STAGE;
#pragma unroll
        for (int ks = 0; ks < 2; ks++) {
            uint32_t ah[4][4], al[4][4], bh[2][4], bl[2][4];
#pragma unroll
            for (int mi = 0; mi < 4; mi++) {
                uint32_t ad = base + (uint32_t)((aRow + mi * 16) * 80 + (aChk + ks * 2) * 16);
                ldsm4(ah[mi], ad);
                ldsm4(al[mi], ad + PLANE);
            }
#pragma unroll
            for (int pr = 0; pr < 2; pr++) {
                uint32_t bd = base + 2 * PLANE +
                              (uint32_t)((wn + pr * 16 + bRowOff) * 80 + (bChk + ks * 2) * 16);
                ldsm4(bh[pr], bd);
                ldsm4(bl[pr], bd + PLANE);
            }
#pragma unroll
            for (int mi = 0; mi < 4; mi++)
#pragma unroll
                for (int ni = 0; ni < 4; ni++) {
                    const int pr = ni >> 1, o = (ni & 1) * 2;
                    mma16816(acc[mi][ni], ah[mi], bh[pr][o], bh[pr][o + 1]);
                    mma16816(acc[mi][ni], ah[mi], bl[pr][o], bl[pr][o + 1]);
                    mma16816(acc[mi][ni], al[mi], bh[pr][o], bh[pr][o + 1]);
                }
        }
    }

    // ---- epilogues ----
    const int l4 = lane >> 2, l2 = (lane & 3) * 2;

    if (MODE == 1) {
#pragma unroll
        for (int mi = 0; mi < 4; mi++) {
            int r0 = rowBase + wr + mi * 16 + l4;
            int b = r0 >> 5;
#pragma unroll
            for (int ni = 0; ni < 4; ni++) {
                int c = colBase + wn + ni * 8 + l2;
                float2 h = *reinterpret_cast<const float2*>(hs + (size_t)b * H_SZ + c);
                float s0 = 1.0f - h.x * h.x, s1 = 1.0f - h.y * h.y;
                uint32_t hi, lo;
                bsplit2(acc[mi][ni][0] * s0, acc[mi][ni][1] * s1, hi, lo);
                *reinterpret_cast<uint32_t*>(U2h + (size_t)r0 * H_SZ + c) = hi;
                *reinterpret_cast<uint32_t*>(U2l + (size_t)r0 * H_SZ + c) = lo;
                bsplit2(acc[mi][ni][2] * s0, acc[mi][ni][3] * s1, hi, lo);
                *reinterpret_cast<uint32_t*>(U2h + (size_t)(r0 + 8) * H_SZ + c) = hi;
                *reinterpret_cast<uint32_t*>(U2l + (size_t)(r0 + 8) * H_SZ + c) = lo;
            }
        }
    } else {
        float p[2] = {0.0f, 0.0f};
#pragma unroll
        for (int mi = 0; mi < 4; mi++) {
            int r0 = rowBase + wr + mi * 16 + l4;
            int b = r0 >> 5, d0 = r0 & 31;
#pragma unroll
            for (int ni = 0; ni < 4; ni++) {
                int c = colBase + wn + ni * 8 + l2;
                float2 h  = *reinterpret_cast<const float2*>(hs + (size_t)b * H_SZ + c);
                float s0 = 1.0f - h.x * h.x, s1 = 1.0f - h.y * h.y;
                float2 w0 = *reinterpret_cast<const float2*>(W3p + (size_t)d0 * H_SZ + c);
                float2 w1 = *reinterpret_cast<const float2*>(W3p + (size_t)(d0 + 8) * H_SZ + c);
                p[mi >> 1] += acc[mi][ni][0] * s0 * w0.x + acc[mi][ni][1] * s1 * w0.y
                            + acc[mi][ni][2] * s0 * w1.x + acc[mi][ni][3] * s1 * w1.y;
            }
        }
#pragma unroll
        for (int j = 0; j < 2; j++) {
            float v = p[j];
#pragma unroll
            for (int o = 16; o > 0; o >>= 1) v += __shfl_xor_sync(0xffffffffu, v, o);
            if (lane == 0) red[warpM * 2 + j][warpN] = v;
        }
        __syncthreads();
        if (tid < 4) {
            float s = red[tid][0] + red[tid][1] + red[tid][2] + red[tid][3];
            g_tpart[blockIdx.x * B_SZ + (rowBase >> 5) + tid] = s;
        }
    }
}

// =====================================================================
// Forward GEMM (bf16-split mma.sync with inline conversion — small cost)
// =====================================================================
#define FPLANE 10240
#define FSBUF  (4 * FPLANE)
#define SMEM_FWD (2 * FSBUF)

__global__ void __launch_bounds__(256, 1)
fwd_gemm(const float* __restrict__ A, const float* __restrict__ W,
         const float* __restrict__ bias, float* __restrict__ C)
{
    extern __shared__ char sm[];
    const uint32_t sb = smem_u32_of(sm);
    const int tid = threadIdx.x, lane = tid & 31, wid = tid >> 5;
    const int warpM = wid >> 2, warpN = wid & 3;
    const int wr = warpM * 64, wn = warpN * 32;
    const int rowBase = blockIdx.y * 128, colBase = blockIdx.x * 128;

    float acc[4][4][4];
#pragma unroll
    for (int a = 0; a < 4; a++)
#pragma unroll
        for (int b = 0; b < 4; b++)
#pragma unroll
            for (int c = 0; c < 4; c++) acc[a][b][c] = 0.0f;

    const int aRow = wr + (lane & 15);
    const int aChk = lane >> 4;
    const int bRowOff = ((lane >> 4) << 3) + (lane & 7);
    const int bChk = (lane >> 3) & 1;

    float4 va[4], vb[4];
    auto LDG = [&](int kt) {
        const int kb = kt * 32;
#pragma unroll
        for (int i = 0; i < 4; i++) {
            int q = tid + i * 256;
            int r = q >> 3, kq = q & 7, k0 = kb + kq * 4;
            va[i] = *reinterpret_cast<const float4*>(A + (size_t)(rowBase + r) * H_SZ + k0);
            vb[i] = *reinterpret_cast<const float4*>(W + (size_t)(colBase + r) * H_SZ + k0);
        }
    };
    auto STS = [&](int s) {
#pragma unroll
        for (int i = 0; i < 4; i++) {
            int q = tid + i * 256;
            int r = q >> 3, kq = q & 7;
            uint32_t off = (uint32_t)(r * 80 + (kq >> 1) * 16 + (kq & 1) * 8);
            uint32_t h0, l0, h1, l1;
            bsplit2(va[i].x, va[i].y, h0, l0);
            bsplit2(va[i].z, va[i].w, h1, l1);
            *reinterpret_cast<uint2*>(sm + s * FSBUF + off)              = make_uint2(h0, h1);
            *reinterpret_cast<uint2*>(sm + s * FSBUF + FPLANE + off)     = make_uint2(l0, l1);
            bsplit2(vb[i].x, vb[i].y, h0, l0);
            bsplit2(vb[i].z, vb[i].w, h1, l1);
            *reinterpret_cast<uint2*>(sm + s * FSBUF + 2 * FPLANE + off) = make_uint2(h0, h1);
            *reinterpret_cast<uint2*>(sm + s * FSBUF + 3 * FPLANE + off) = make_uint2(l0, l1);
        }
    };

    LDG(0); STS(0);
    __syncthreads();

    int cur = 0;
    for (int kt = 0; kt < 32; kt++) {
        if (kt + 1 < 32) LDG(kt + 1);
        const uint32_t base = sb + cur * FSBUF;
#pragma unroll
        for (int ks = 0; ks < 2; ks++) {
            uint32_t ah[4][4], al[4][4], bh[2][4], bl[2][4];
#pragma unroll
            for (int mi = 0; mi < 4; mi++) {
                uint32_t ad = base + (uint32_t)((aRow + mi * 16) * 80 + (aChk + ks * 2) * 16);
                ldsm4(ah[mi], ad);
                ldsm4(al[mi], ad + FPLANE);
            }
#pragma unroll
            for (int pr = 0; pr < 2; pr++) {
                uint32_t bd = base + 2 * FPLANE +
                              (uint32_t)((wn + pr * 16 + bRowOff) * 80 + (bChk + ks * 2) * 16);
                ldsm4(bh[pr], bd);
                ldsm4(bl[pr], bd + FPLANE);
            }
#pragma unroll
            for (int mi = 0; mi < 4; mi++)
#pragma unroll
                for (int ni = 0; ni < 4; ni++) {
                    const int pr = ni >> 1, o = (ni & 1) * 2;
                    mma16816(acc[mi][ni], ah[mi], bh[pr][o], bh[pr][o + 1]);
                    mma16816(acc[mi][ni], ah[mi], bl[pr][o], bl[pr][o + 1]);
                    mma16816(acc[mi][ni], al[mi], bh[pr][o], bh[pr][o + 1]);
                }
        }
        if (kt + 1 < 32) {
            int nxt = cur ^ 1;
            STS(nxt);
            __syncthreads();
            cur = nxt;
        }
    }

    const int l4 = lane >> 2, l2 = (lane & 3) * 2;
#pragma unroll
    for (int mi = 0; mi < 4; mi++) {
        int r0 = rowBase + wr + mi * 16 + l4;
#pragma unroll
        for (int ni = 0; ni < 4; ni++) {
            int c = colBase + wn + ni * 8 + l2;
            float2 bb = *reinterpret_cast<const float2*>(bias + c);
            *reinterpret_cast<float2*>(C + (size_t)r0 * H_SZ + c) =
                make_float2(tanhf(acc[mi][ni][0] + bb.x), tanhf(acc[mi][ni][1] + bb.y));
            *reinterpret_cast<float2*>(C + (size_t)(r0 + 8) * H_SZ + c) =
                make_float2(tanhf(acc[mi][ni][2] + bb.x), tanhf(acc[mi][ni][3] + bb.y));
        }
    }
}

// =====================================================================
// prep kernels
// =====================================================================

// W fp32 [H,H] -> hi/lo bf16 planes
__global__ void conv_w(const float* __restrict__ W, __nv_bfloat16* __restrict__ Wh,
                       __nv_bfloat16* __restrict__ Wl)
{
    int i = blockIdx.x * blockDim.x + threadIdx.x;   // over H*H/4
    float4 v = reinterpret_cast<const float4*>(W)[i];
    uint32_t h0, l0, h1, l1;
    bsplit2(v.x, v.y, h0, l0);
    bsplit2(v.z, v.w, h1, l1);
    reinterpret_cast<uint2*>(Wh)[i] = make_uint2(h0, h1);
    reinterpret_cast<uint2*>(Wl)[i] = make_uint2(l0, l1);
}

// W0 [H,33] -> W0T [32][H] (one-shot, tiny)
__global__ void conv_w0t(const float* __restrict__ W0, float* __restrict__ W0T)
{
    int idx = blockIdx.x * blockDim.x + threadIdx.x;   // 32768
    int d = idx >> 10, k = idx & (H_SZ - 1);
    W0T[idx] = W0[k * 33 + d];
}

// U1[(b,d),k] = (1-h1[b,k]^2) * W0T[d,k] -> hi/lo bf16. Fully coalesced.
__global__ void __launch_bounds__(256)
prep_u1(const float* __restrict__ h1, const float* __restrict__ W0T,
        __nv_bfloat16* __restrict__ U1h, __nv_bfloat16* __restrict__ U1l)
{
    __shared__ float s1[H_SZ];
    const int b = blockIdx.x, tid = threadIdx.x;
    {
        float4 h = *reinterpret_cast<const float4*>(h1 + (size_t)b * H_SZ + tid * 4);
        s1[tid * 4 + 0] = 1.0f - h.x * h.x;
        s1[tid * 4 + 1] = 1.0f - h.y * h.y;
        s1[tid * 4 + 2] = 1.0f - h.z * h.z;
        s1[tid * 4 + 3] = 1.0f - h.w * h.w;
    }
    __syncthreads();
#pragma unroll 1
    for (int d = 0; d < 32; d++) {
        float4 w = *reinterpret_cast<const float4*>(W0T + d * H_SZ + tid * 4);
        float u0 = s1[tid * 4 + 0] * w.x;
        float u1 = s1[tid * 4 + 1] * w.y;
        float u2 = s1[tid * 4 + 2] * w.z;
        float u3 = s1[tid * 4 + 3] * w.w;
        uint32_t h0, l0, h1b, l1;
        bsplit2(u0, u1, h0, l0);
        bsplit2(u2, u3, h1b, l1);
        size_t base = ((size_t)(b * 32 + d) << 10) + tid * 4;
        *reinterpret_cast<uint2*>(U1h + base) = make_uint2(h0, h1b);
        *reinterpret_cast<uint2*>(U1l + base) = make_uint2(l0, l1);
    }
}

// h1 = tanh([z|t] @ W0^T + b0)
__global__ void layer0_kernel(const float* __restrict__ t, const float* __restrict__ z,
                              const float* __restrict__ W0, const float* __restrict__ b0,
                              float* __restrict__ h1)
{
    int idx = blockIdx.x * blockDim.x + threadIdx.x;
    int j = idx & (H_SZ - 1);
    int b = idx >> 10;
    const float* w  = W0 + j * 33;
    const float* zr = z + b * D_SZ;
    float acc = b0[j] + t[0] * w[32];
#pragma unroll
    for (int d = 0; d < 32; d++) acc = fmaf(zr[d], w[d], acc);
    h1[idx] = tanhf(acc);
}

// out = h3 @ W3^T + b3
__global__ void __launch_bounds__(256, 4)
out_kernel2(const float* __restrict__ h3, const float* __restrict__ W3,
            const float* __restrict__ b3, float* __restrict__ out)
{
    const int b = blockIdx.x;
    const int wid = threadIdx.x >> 5, lid = threadIdx.x & 31;
    const float* h = h3 + (size_t)b * H_SZ;
#pragma unroll
    for (int dd = 0; dd < 4; dd++) {
        const int d = wid * 4 + dd;
        const float* w = W3 + (size_t)d * H_SZ;
        float acc = 0.0f;
#pragma unroll 4
        for (int k = lid; k < H_SZ; k += 32) acc = fmaf(h[k], w[k], acc);
#pragma unroll
        for (int o = 16; o > 0; o >>= 1) acc += __shfl_xor_sync(0xffffffffu, acc, o);
        if (lid == 0) out[b * D_SZ + d] = acc + b3[d];
    }
}

// divv[b] = -(sum of 8 j-tile partials)
__global__ void fin_kernel(float* __restrict__ out)
{
    int b = blockIdx.x * blockDim.x + threadIdx.x;
    if (b < B_SZ) {
        float s = 0.0f;
#pragma unroll
        for (int x = 0; x < 8; x++) s += g_tpart[x * B_SZ + b];
        out[B_SZ * D_SZ + b] = -s;
    }
}

// ---------------- launch ----------------
extern "C" void kernel_launch(void* const* d_in, const int* in_sizes, int n_in,
                              void* d_out, int out_size)
{
    const float* t  = (const float*)d_in[0];
    const float* z  = (const float*)d_in[1];
    const float* W0 = (const float*)d_in[2];
    const float* b0 = (const float*)d_in[3];
    const float* W1 = (const float*)d_in[4];
    const float* b1 = (const float*)d_in[5];
    const float* W2 = (const float*)d_in[6];
    const float* b2 = (const float*)d_in[7];
    const float* W3 = (const float*)d_in[8];
    const float* b3 = (const float*)d_in[9];
    float* out = (float*)d_out;

    float *ph1, *ph2, *ph3, *pW0T;
    __nv_bfloat16 *pU1h, *pU1l, *pU2h, *pU2l, *pW1h, *pW1l, *pW2h, *pW2l;
    cudaGetSymbolAddress((void**)&ph1, g_h1);
    cudaGetSymbolAddress((void**)&ph2, g_h2);
    cudaGetSymbolAddress((void**)&ph3, g_h3);
    cudaGetSymbolAddress((void**)&pW0T, g_W0T);
    cudaGetSymbolAddress((void**)&pU1h, g_U1h);
    cudaGetSymbolAddress((void**)&pU1l, g_U1l);
    cudaGetSymbolAddress((void**)&pU2h, g_U2h);
    cudaGetSymbolAddress((void**)&pU2l, g_U2l);
    cudaGetSymbolAddress((void**)&pW1h, g_W1h);
    cudaGetSymbolAddress((void**)&pW1l, g_W1l);
    cudaGetSymbolAddress((void**)&pW2h, g_W2h);
    cudaGetSymbolAddress((void**)&pW2l, g_W2l);

    cudaFuncSetAttribute(fwd_gemm,    cudaFuncAttributeMaxDynamicSharedMemorySize, SMEM_FWD);
    cudaFuncSetAttribute(tan_bf16<1>, cudaFuncAttributeMaxDynamicSharedMemorySize, SMEM_TAN);
    cudaFuncSetAttribute(tan_bf16<2>, cudaFuncAttributeMaxDynamicSharedMemorySize, SMEM_TAN);

    // prep
    layer0_kernel<<<(B_SZ * H_SZ) / 256, 256>>>(t, z, W0, b0, ph1);
    conv_w0t<<<(D_SZ * H_SZ) / 256, 256>>>(W0, pW0T);
    conv_w<<<(H_SZ * H_SZ / 4) / 256, 256>>>(W1, pW1h, pW1l);
    conv_w<<<(H_SZ * H_SZ / 4) / 256, 256>>>(W2, pW2h, pW2l);
    prep_u1<<<B_SZ, 256>>>(ph1, pW0T, pU1h, pU1l);

    // forward
    dim3 gF(H_SZ / 128, B_SZ / 128);   // (8, 32)
    fwd_gemm<<<gF, 256, SMEM_FWD>>>(ph1, W1, b1, ph2);
    fwd_gemm<<<gF, 256, SMEM_FWD>>>(ph2, W2, b2, ph3);
    out_kernel2<<<B_SZ, 256>>>(ph3, W3, b3, out);

    // tangent chain (pure-bf16 tensor-core pipeline)
    dim3 gT(H_SZ / 128, MT / 128);     // (8, 1024)
    tan_bf16<1><<<gT, 256, SMEM_TAN>>>(pU1h, pU1l, pW1h, pW1l, ph2, nullptr, pU2h, pU2l);
    tan_bf16<2><<<gT, 256, SMEM_TAN>>>(pU2h, pU2l, pW2h, pW2l, ph3, W3, nullptr, nullptr);

    fin_kernel<<<(B_SZ + 255) / 256, 256>>>(out);
}